// round 1
// baseline (speedup 1.0000x reference)
#include <cuda_runtime.h>
#include <math.h>

#define NR   8192
#define DIM  64
#define HID  512
#define LAT  128

// Scratch (device globals — allocation-free per harness rules)
__device__ float g_H1[2 * NR * HID];   // 32 MB
__device__ float g_H2[2 * NR * HID];   // 32 MB
__device__ float g_Z [2 * NR * LAT];   //  8 MB

// ---------------------------------------------------------------------------
// Generic tiled SGEMM: C[M,N] = act(A[M,K] @ W[K,N] + bias)
// Block tile 128x128, BK=16, 256 threads, 8x8 microtile (split 4+4).
// Requires M%128==0, N%128==0, K%16==0 (true for all layers here).
// ---------------------------------------------------------------------------
template<bool RELU>
__global__ __launch_bounds__(256) void gemm_bias_act(
    const float* __restrict__ A, const float* __restrict__ W,
    const float* __restrict__ bias, float* __restrict__ C,
    int K, int N)
{
    __shared__ float As[16][128];   // As[k][m]
    __shared__ float Bs[16][128];   // Bs[k][n]
    const int tid = threadIdx.x;
    const int tx = tid & 15, ty = tid >> 4;
    const int bm = blockIdx.y << 7, bn = blockIdx.x << 7;

    float acc[8][8];
#pragma unroll
    for (int i = 0; i < 8; i++)
#pragma unroll
        for (int j = 0; j < 8; j++) acc[i][j] = 0.f;

    const int ar = tid >> 1;          // 0..127  (A tile row)
    const int ak = (tid & 1) << 3;    // 0 or 8  (A tile k-seg)
    const int wk = ty;                // 0..15   (W tile k-row)
    const int wn = tx << 3;           // 0..120  (W tile n-seg)

    for (int k0 = 0; k0 < K; k0 += 16) {
        const float* ap = A + (size_t)(bm + ar) * K + (k0 + ak);
        float4 v0 = *(const float4*)ap;
        float4 v1 = *(const float4*)(ap + 4);
        As[ak+0][ar] = v0.x; As[ak+1][ar] = v0.y; As[ak+2][ar] = v0.z; As[ak+3][ar] = v0.w;
        As[ak+4][ar] = v1.x; As[ak+5][ar] = v1.y; As[ak+6][ar] = v1.z; As[ak+7][ar] = v1.w;

        const float* wp = W + (size_t)(k0 + wk) * N + (bn + wn);
        *(float4*)&Bs[wk][wn]     = *(const float4*)wp;
        *(float4*)&Bs[wk][wn + 4] = *(const float4*)(wp + 4);
        __syncthreads();

#pragma unroll
        for (int kk = 0; kk < 16; kk++) {
            float4 a0 = *(const float4*)&As[kk][(ty << 2)];
            float4 a1 = *(const float4*)&As[kk][64 + (ty << 2)];
            float4 b0 = *(const float4*)&Bs[kk][(tx << 2)];
            float4 b1 = *(const float4*)&Bs[kk][64 + (tx << 2)];
            float aa[8] = {a0.x,a0.y,a0.z,a0.w,a1.x,a1.y,a1.z,a1.w};
            float bb[8] = {b0.x,b0.y,b0.z,b0.w,b1.x,b1.y,b1.z,b1.w};
#pragma unroll
            for (int i = 0; i < 8; i++)
#pragma unroll
                for (int j = 0; j < 8; j++)
                    acc[i][j] = fmaf(aa[i], bb[j], acc[i][j]);
        }
        __syncthreads();
    }

    float4 bv0 = *(const float4*)&bias[bn + (tx << 2)];
    float4 bv1 = *(const float4*)&bias[bn + 64 + (tx << 2)];
    float bb[8] = {bv0.x,bv0.y,bv0.z,bv0.w,bv1.x,bv1.y,bv1.z,bv1.w};
#pragma unroll
    for (int i = 0; i < 8; i++) {
        int row = bm + ((i < 4) ? (ty * 4 + i) : (64 + ty * 4 + i - 4));
        float o[8];
#pragma unroll
        for (int j = 0; j < 8; j++) {
            float v = acc[i][j] + bb[j];
            o[j] = RELU ? fmaxf(v, 0.f) : v;
        }
        float* cp = C + (size_t)row * N + bn;
        *(float4*)(cp + (tx << 2))      = make_float4(o[0], o[1], o[2], o[3]);
        *(float4*)(cp + 64 + (tx << 2)) = make_float4(o[4], o[5], o[6], o[7]);
    }
}

// ---------------------------------------------------------------------------
// Last encoder layer (K=512 -> N=128) with fused bias + row L2-normalize.
// One block covers the full LATENT=128 columns, so the row norm reduces
// entirely within the block.
// ---------------------------------------------------------------------------
__global__ __launch_bounds__(256) void gemm_last_norm(
    const float* __restrict__ A, const float* __restrict__ W,
    const float* __restrict__ bias, float* __restrict__ Z, int K)
{
    const int N = LAT;  // 128; bn == 0 (gridDim.x == 1)
    __shared__ float As[16][128];
    __shared__ float Bs[16][128];
    __shared__ float red[128][17];  // [row][tx partial], col 16 = inv-norm
    const int tid = threadIdx.x;
    const int tx = tid & 15, ty = tid >> 4;
    const int bm = blockIdx.y << 7;

    float acc[8][8];
#pragma unroll
    for (int i = 0; i < 8; i++)
#pragma unroll
        for (int j = 0; j < 8; j++) acc[i][j] = 0.f;

    const int ar = tid >> 1;
    const int ak = (tid & 1) << 3;
    const int wk = ty;
    const int wn = tx << 3;

    for (int k0 = 0; k0 < K; k0 += 16) {
        const float* ap = A + (size_t)(bm + ar) * K + (k0 + ak);
        float4 v0 = *(const float4*)ap;
        float4 v1 = *(const float4*)(ap + 4);
        As[ak+0][ar] = v0.x; As[ak+1][ar] = v0.y; As[ak+2][ar] = v0.z; As[ak+3][ar] = v0.w;
        As[ak+4][ar] = v1.x; As[ak+5][ar] = v1.y; As[ak+6][ar] = v1.z; As[ak+7][ar] = v1.w;

        const float* wp = W + (size_t)(k0 + wk) * N + wn;
        *(float4*)&Bs[wk][wn]     = *(const float4*)wp;
        *(float4*)&Bs[wk][wn + 4] = *(const float4*)(wp + 4);
        __syncthreads();

#pragma unroll
        for (int kk = 0; kk < 16; kk++) {
            float4 a0 = *(const float4*)&As[kk][(ty << 2)];
            float4 a1 = *(const float4*)&As[kk][64 + (ty << 2)];
            float4 b0 = *(const float4*)&Bs[kk][(tx << 2)];
            float4 b1 = *(const float4*)&Bs[kk][64 + (tx << 2)];
            float aa[8] = {a0.x,a0.y,a0.z,a0.w,a1.x,a1.y,a1.z,a1.w};
            float bb[8] = {b0.x,b0.y,b0.z,b0.w,b1.x,b1.y,b1.z,b1.w};
#pragma unroll
            for (int i = 0; i < 8; i++)
#pragma unroll
                for (int j = 0; j < 8; j++)
                    acc[i][j] = fmaf(aa[i], bb[j], acc[i][j]);
        }
        __syncthreads();
    }

    // bias, then per-row sum of squares (partial over this thread's 8 cols)
    float4 bv0 = *(const float4*)&bias[(tx << 2)];
    float4 bv1 = *(const float4*)&bias[64 + (tx << 2)];
    float bb[8] = {bv0.x,bv0.y,bv0.z,bv0.w,bv1.x,bv1.y,bv1.z,bv1.w};
#pragma unroll
    for (int i = 0; i < 8; i++) {
        int rl = (i < 4) ? (ty * 4 + i) : (64 + ty * 4 + i - 4);
        float s = 0.f;
#pragma unroll
        for (int j = 0; j < 8; j++) {
            acc[i][j] += bb[j];
            s = fmaf(acc[i][j], acc[i][j], s);
        }
        red[rl][tx] = s;
    }
    __syncthreads();

    if (tid < 128) {
        float s = 0.f;
#pragma unroll
        for (int t = 0; t < 16; t++) s += red[tid][t];
        float nrm = sqrtf(s);
        red[tid][16] = 1.f / fmaxf(nrm, 1e-12f);
    }
    __syncthreads();

#pragma unroll
    for (int i = 0; i < 8; i++) {
        int rl  = (i < 4) ? (ty * 4 + i) : (64 + ty * 4 + i - 4);
        float inv = red[rl][16];
        float* zp = Z + (size_t)(bm + rl) * N;
        *(float4*)(zp + (tx << 2)) =
            make_float4(acc[i][0]*inv, acc[i][1]*inv, acc[i][2]*inv, acc[i][3]*inv);
        *(float4*)(zp + 64 + (tx << 2)) =
            make_float4(acc[i][4]*inv, acc[i][5]*inv, acc[i][6]*inv, acc[i][7]*inv);
    }
}

// ---------------------------------------------------------------------------
// Final similarity GEMM: C[8192,8192] = ZA @ ZB^T, K = 128.
// Both ZA, ZB are [8192,128] row-major, so both tiles load like "A".
// ---------------------------------------------------------------------------
__global__ __launch_bounds__(256) void gemm_nt(
    const float* __restrict__ ZA, const float* __restrict__ ZB,
    float* __restrict__ C)
{
    __shared__ float As[16][128];
    __shared__ float Bs[16][128];
    const int tid = threadIdx.x;
    const int tx = tid & 15, ty = tid >> 4;
    const int bm = blockIdx.y << 7, bn = blockIdx.x << 7;

    float acc[8][8];
#pragma unroll
    for (int i = 0; i < 8; i++)
#pragma unroll
        for (int j = 0; j < 8; j++) acc[i][j] = 0.f;

    const int ar = tid >> 1;
    const int ak = (tid & 1) << 3;

    for (int k0 = 0; k0 < LAT; k0 += 16) {
        const float* ap = ZA + (size_t)(bm + ar) * LAT + (k0 + ak);
        float4 v0 = *(const float4*)ap;
        float4 v1 = *(const float4*)(ap + 4);
        As[ak+0][ar] = v0.x; As[ak+1][ar] = v0.y; As[ak+2][ar] = v0.z; As[ak+3][ar] = v0.w;
        As[ak+4][ar] = v1.x; As[ak+5][ar] = v1.y; As[ak+6][ar] = v1.z; As[ak+7][ar] = v1.w;

        const float* bp = ZB + (size_t)(bn + ar) * LAT + (k0 + ak);
        float4 u0 = *(const float4*)bp;
        float4 u1 = *(const float4*)(bp + 4);
        Bs[ak+0][ar] = u0.x; Bs[ak+1][ar] = u0.y; Bs[ak+2][ar] = u0.z; Bs[ak+3][ar] = u0.w;
        Bs[ak+4][ar] = u1.x; Bs[ak+5][ar] = u1.y; Bs[ak+6][ar] = u1.z; Bs[ak+7][ar] = u1.w;
        __syncthreads();

#pragma unroll
        for (int kk = 0; kk < 16; kk++) {
            float4 a0 = *(const float4*)&As[kk][(ty << 2)];
            float4 a1 = *(const float4*)&As[kk][64 + (ty << 2)];
            float4 b0 = *(const float4*)&Bs[kk][(tx << 2)];
            float4 b1 = *(const float4*)&Bs[kk][64 + (tx << 2)];
            float aa[8] = {a0.x,a0.y,a0.z,a0.w,a1.x,a1.y,a1.z,a1.w};
            float bb[8] = {b0.x,b0.y,b0.z,b0.w,b1.x,b1.y,b1.z,b1.w};
#pragma unroll
            for (int i = 0; i < 8; i++)
#pragma unroll
                for (int j = 0; j < 8; j++)
                    acc[i][j] = fmaf(aa[i], bb[j], acc[i][j]);
        }
        __syncthreads();
    }

#pragma unroll
    for (int i = 0; i < 8; i++) {
        int row = bm + ((i < 4) ? (ty * 4 + i) : (64 + ty * 4 + i - 4));
        float* cp = C + (size_t)row * NR + bn;
        *(float4*)(cp + (tx << 2))      = make_float4(acc[i][0], acc[i][1], acc[i][2], acc[i][3]);
        *(float4*)(cp + 64 + (tx << 2)) = make_float4(acc[i][4], acc[i][5], acc[i][6], acc[i][7]);
    }
}

// ---------------------------------------------------------------------------
extern "C" void kernel_launch(void* const* d_in, const int* in_sizes, int n_in,
                              void* d_out, int out_size)
{
    const float* x  = (const float*)d_in[0];
    const float* y  = (const float*)d_in[1];
    const float* W1 = (const float*)d_in[2];
    const float* b1 = (const float*)d_in[3];
    const float* W2 = (const float*)d_in[4];
    const float* b2 = (const float*)d_in[5];
    const float* W3 = (const float*)d_in[6];
    const float* b3 = (const float*)d_in[7];
    float* out = (float*)d_out;

    float *H1, *H2, *Z;
    cudaGetSymbolAddress((void**)&H1, g_H1);
    cudaGetSymbolAddress((void**)&H2, g_H2);
    cudaGetSymbolAddress((void**)&Z,  g_Z);

    // Layer 1: relu(x@W1+b1) and relu(y@W1+b1) -> H1 [16384, 512]
    dim3 g1(HID / 128, NR / 128);
    gemm_bias_act<true><<<g1, 256>>>(x, W1, b1, H1, DIM, HID);
    gemm_bias_act<true><<<g1, 256>>>(y, W1, b1, H1 + (size_t)NR * HID, DIM, HID);

    // Layer 2: relu(H1@W2+b2) -> H2 [16384, 512]
    dim3 g2(HID / 128, 2 * NR / 128);
    gemm_bias_act<true><<<g2, 256>>>(H1, W2, b2, H2, HID, HID);

    // Layer 3 + L2 normalize: Z = l2norm(H2@W3+b3) [16384, 128]
    dim3 g3(1, 2 * NR / 128);
    gemm_last_norm<<<g3, 256>>>(H2, W3, b3, Z, HID);

    // Similarity: out = Zx @ Zy^T  (TEMP = 1.0)
    dim3 g4(NR / 128, NR / 128);
    gemm_nt<<<g4, 256>>>(Z, Z + (size_t)NR * LAT, out);
}

// round 2
// speedup vs baseline: 1.0763x; 1.0763x over previous
#include <cuda_runtime.h>
#include <math.h>

#define NR   8192
#define DIM  64
#define HID  512
#define LAT  128

// Scratch (device globals — allocation-free per harness rules)
__device__ float g_H1[2 * NR * HID];   // 32 MB
__device__ float g_H2[2 * NR * HID];   // 32 MB
__device__ float g_Z [2 * NR * LAT];   //  8 MB

// ---------------------------------------------------------------------------
// f32x2 packed-FMA helpers (sm_103a FFMA2 — ptxas will not auto-fuse)
// ---------------------------------------------------------------------------
__device__ __forceinline__ unsigned long long pack2_dup(float v) {
    unsigned long long r;
    unsigned u = __float_as_uint(v);
    asm("mov.b64 %0, {%1, %1};" : "=l"(r) : "r"(u));
    return r;
}
__device__ __forceinline__ void fma2(unsigned long long& d,
                                     unsigned long long a,
                                     unsigned long long b) {
    asm("fma.rn.f32x2 %0, %1, %2, %3;" : "=l"(d) : "l"(a), "l"(b), "l"(d));
}
__device__ __forceinline__ float2 unpack2(unsigned long long v) {
    unsigned lo, hi;
    asm("mov.b64 {%0, %1}, %2;" : "=r"(lo), "=r"(hi) : "l"(v));
    return make_float2(__uint_as_float(lo), __uint_as_float(hi));
}

// ---------------------------------------------------------------------------
// Generic tiled SGEMM: C[M,N] = act(A[M,K] @ W[K,N] + bias)
// Block tile 128x128, BK=16, 256 threads, 8x8 microtile, f32x2 accumulators.
// ---------------------------------------------------------------------------
template<bool RELU>
__global__ __launch_bounds__(256) void gemm_bias_act(
    const float* __restrict__ A, const float* __restrict__ W,
    const float* __restrict__ bias, float* __restrict__ C,
    int K, int N)
{
    __shared__ float As[16][128];   // As[k][m]
    __shared__ float Bs[16][128];   // Bs[k][n]
    const int tid = threadIdx.x;
    const int tx = tid & 15, ty = tid >> 4;
    const int bm = blockIdx.y << 7, bn = blockIdx.x << 7;

    unsigned long long acc2[8][4];
#pragma unroll
    for (int i = 0; i < 8; i++)
#pragma unroll
        for (int j = 0; j < 4; j++) acc2[i][j] = 0ull;

    const int ar = tid >> 1;          // 0..127
    const int ak = (tid & 1) << 3;    // 0 or 8
    const int wk = ty;                // 0..15
    const int wn = tx << 3;           // 0..120

    for (int k0 = 0; k0 < K; k0 += 16) {
        const float* ap = A + (size_t)(bm + ar) * K + (k0 + ak);
        float4 v0 = *(const float4*)ap;
        float4 v1 = *(const float4*)(ap + 4);
        As[ak+0][ar] = v0.x; As[ak+1][ar] = v0.y; As[ak+2][ar] = v0.z; As[ak+3][ar] = v0.w;
        As[ak+4][ar] = v1.x; As[ak+5][ar] = v1.y; As[ak+6][ar] = v1.z; As[ak+7][ar] = v1.w;

        const float* wp = W + (size_t)(k0 + wk) * N + (bn + wn);
        *(float4*)&Bs[wk][wn]     = *(const float4*)wp;
        *(float4*)&Bs[wk][wn + 4] = *(const float4*)(wp + 4);
        __syncthreads();

#pragma unroll
        for (int kk = 0; kk < 16; kk++) {
            float4 a0 = *(const float4*)&As[kk][(ty << 2)];
            float4 a1 = *(const float4*)&As[kk][64 + (ty << 2)];
            unsigned long long aa2[8];
            aa2[0] = pack2_dup(a0.x); aa2[1] = pack2_dup(a0.y);
            aa2[2] = pack2_dup(a0.z); aa2[3] = pack2_dup(a0.w);
            aa2[4] = pack2_dup(a1.x); aa2[5] = pack2_dup(a1.y);
            aa2[6] = pack2_dup(a1.z); aa2[7] = pack2_dup(a1.w);
            ulonglong2 q0 = *(const ulonglong2*)&Bs[kk][(tx << 2)];
            ulonglong2 q1 = *(const ulonglong2*)&Bs[kk][64 + (tx << 2)];
            unsigned long long bb2[4] = {q0.x, q0.y, q1.x, q1.y};
#pragma unroll
            for (int i = 0; i < 8; i++)
#pragma unroll
                for (int j = 0; j < 4; j++)
                    fma2(acc2[i][j], aa2[i], bb2[j]);
        }
        __syncthreads();
    }

    float4 bv0 = *(const float4*)&bias[bn + (tx << 2)];
    float4 bv1 = *(const float4*)&bias[bn + 64 + (tx << 2)];
    float bb[8] = {bv0.x,bv0.y,bv0.z,bv0.w,bv1.x,bv1.y,bv1.z,bv1.w};
#pragma unroll
    for (int i = 0; i < 8; i++) {
        int row = bm + ((i < 4) ? (ty * 4 + i) : (64 + ty * 4 + i - 4));
        float o[8];
#pragma unroll
        for (int j = 0; j < 4; j++) {
            float2 p = unpack2(acc2[i][j]);
            o[2*j+0] = p.x + bb[2*j+0];
            o[2*j+1] = p.y + bb[2*j+1];
        }
        if (RELU) {
#pragma unroll
            for (int j = 0; j < 8; j++) o[j] = fmaxf(o[j], 0.f);
        }
        float* cp = C + (size_t)row * N + bn;
        *(float4*)(cp + (tx << 2))      = make_float4(o[0], o[1], o[2], o[3]);
        *(float4*)(cp + 64 + (tx << 2)) = make_float4(o[4], o[5], o[6], o[7]);
    }
}

// ---------------------------------------------------------------------------
// Last encoder layer (K=512 -> N=128) + fused bias + row L2-normalize.
// 64-row x 128-col tiles (grid = 256 blocks for better SM balance).
// Microtile 4x8 per thread.
// ---------------------------------------------------------------------------
__global__ __launch_bounds__(256) void gemm_last_norm(
    const float* __restrict__ A, const float* __restrict__ W,
    const float* __restrict__ bias, float* __restrict__ Z, int K)
{
    const int N = LAT;  // 128
    __shared__ float As[16][64];
    __shared__ float Bs[16][128];
    __shared__ float red[64][17];
    const int tid = threadIdx.x;
    const int tx = tid & 15, ty = tid >> 4;
    const int bm = blockIdx.x << 6;

    unsigned long long acc2[4][4];
#pragma unroll
    for (int i = 0; i < 4; i++)
#pragma unroll
        for (int j = 0; j < 4; j++) acc2[i][j] = 0ull;

    const int ar = tid >> 2;          // 0..63
    const int ak = (tid & 3) << 2;    // 0,4,8,12
    const int wk = ty;
    const int wn = tx << 3;

    for (int k0 = 0; k0 < K; k0 += 16) {
        const float* ap = A + (size_t)(bm + ar) * K + (k0 + ak);
        float4 v0 = *(const float4*)ap;
        As[ak+0][ar] = v0.x; As[ak+1][ar] = v0.y; As[ak+2][ar] = v0.z; As[ak+3][ar] = v0.w;

        const float* wp = W + (size_t)(k0 + wk) * N + wn;
        *(float4*)&Bs[wk][wn]     = *(const float4*)wp;
        *(float4*)&Bs[wk][wn + 4] = *(const float4*)(wp + 4);
        __syncthreads();

#pragma unroll
        for (int kk = 0; kk < 16; kk++) {
            float4 a0 = *(const float4*)&As[kk][(ty << 2)];
            unsigned long long aa2[4];
            aa2[0] = pack2_dup(a0.x); aa2[1] = pack2_dup(a0.y);
            aa2[2] = pack2_dup(a0.z); aa2[3] = pack2_dup(a0.w);
            ulonglong2 q0 = *(const ulonglong2*)&Bs[kk][(tx << 2)];
            ulonglong2 q1 = *(const ulonglong2*)&Bs[kk][64 + (tx << 2)];
            unsigned long long bb2[4] = {q0.x, q0.y, q1.x, q1.y};
#pragma unroll
            for (int i = 0; i < 4; i++)
#pragma unroll
                for (int j = 0; j < 4; j++)
                    fma2(acc2[i][j], aa2[i], bb2[j]);
        }
        __syncthreads();
    }

    float4 bv0 = *(const float4*)&bias[(tx << 2)];
    float4 bv1 = *(const float4*)&bias[64 + (tx << 2)];
    float bb[8] = {bv0.x,bv0.y,bv0.z,bv0.w,bv1.x,bv1.y,bv1.z,bv1.w};

    float o[4][8];
#pragma unroll
    for (int i = 0; i < 4; i++) {
        float s = 0.f;
#pragma unroll
        for (int j = 0; j < 4; j++) {
            float2 p = unpack2(acc2[i][j]);
            o[i][2*j+0] = p.x + bb[2*j+0];
            o[i][2*j+1] = p.y + bb[2*j+1];
        }
#pragma unroll
        for (int j = 0; j < 8; j++) s = fmaf(o[i][j], o[i][j], s);
        red[ty * 4 + i][tx] = s;
    }
    __syncthreads();

    if (tid < 64) {
        float s = 0.f;
#pragma unroll
        for (int t = 0; t < 16; t++) s += red[tid][t];
        red[tid][16] = 1.f / fmaxf(sqrtf(s), 1e-12f);
    }
    __syncthreads();

#pragma unroll
    for (int i = 0; i < 4; i++) {
        int rl = ty * 4 + i;
        float inv = red[rl][16];
        float* zp = Z + (size_t)(bm + rl) * N;
        *(float4*)(zp + (tx << 2)) =
            make_float4(o[i][0]*inv, o[i][1]*inv, o[i][2]*inv, o[i][3]*inv);
        *(float4*)(zp + 64 + (tx << 2)) =
            make_float4(o[i][4]*inv, o[i][5]*inv, o[i][6]*inv, o[i][7]*inv);
    }
}

// ---------------------------------------------------------------------------
// Final similarity GEMM: C[8192,8192] = ZA @ ZB^T, K = 128 (both row-major).
// ---------------------------------------------------------------------------
__global__ __launch_bounds__(256) void gemm_nt(
    const float* __restrict__ ZA, const float* __restrict__ ZB,
    float* __restrict__ C)
{
    __shared__ float As[16][128];
    __shared__ float Bs[16][128];
    const int tid = threadIdx.x;
    const int tx = tid & 15, ty = tid >> 4;
    const int bm = blockIdx.y << 7, bn = blockIdx.x << 7;

    unsigned long long acc2[8][4];
#pragma unroll
    for (int i = 0; i < 8; i++)
#pragma unroll
        for (int j = 0; j < 4; j++) acc2[i][j] = 0ull;

    const int ar = tid >> 1;
    const int ak = (tid & 1) << 3;

    for (int k0 = 0; k0 < LAT; k0 += 16) {
        const float* ap = ZA + (size_t)(bm + ar) * LAT + (k0 + ak);
        float4 v0 = *(const float4*)ap;
        float4 v1 = *(const float4*)(ap + 4);
        As[ak+0][ar] = v0.x; As[ak+1][ar] = v0.y; As[ak+2][ar] = v0.z; As[ak+3][ar] = v0.w;
        As[ak+4][ar] = v1.x; As[ak+5][ar] = v1.y; As[ak+6][ar] = v1.z; As[ak+7][ar] = v1.w;

        const float* bp = ZB + (size_t)(bn + ar) * LAT + (k0 + ak);
        float4 u0 = *(const float4*)bp;
        float4 u1 = *(const float4*)(bp + 4);
        Bs[ak+0][ar] = u0.x; Bs[ak+1][ar] = u0.y; Bs[ak+2][ar] = u0.z; Bs[ak+3][ar] = u0.w;
        Bs[ak+4][ar] = u1.x; Bs[ak+5][ar] = u1.y; Bs[ak+6][ar] = u1.z; Bs[ak+7][ar] = u1.w;
        __syncthreads();

#pragma unroll
        for (int kk = 0; kk < 16; kk++) {
            float4 a0 = *(const float4*)&As[kk][(ty << 2)];
            float4 a1 = *(const float4*)&As[kk][64 + (ty << 2)];
            unsigned long long aa2[8];
            aa2[0] = pack2_dup(a0.x); aa2[1] = pack2_dup(a0.y);
            aa2[2] = pack2_dup(a0.z); aa2[3] = pack2_dup(a0.w);
            aa2[4] = pack2_dup(a1.x); aa2[5] = pack2_dup(a1.y);
            aa2[6] = pack2_dup(a1.z); aa2[7] = pack2_dup(a1.w);
            ulonglong2 q0 = *(const ulonglong2*)&Bs[kk][(tx << 2)];
            ulonglong2 q1 = *(const ulonglong2*)&Bs[kk][64 + (tx << 2)];
            unsigned long long bb2[4] = {q0.x, q0.y, q1.x, q1.y};
#pragma unroll
            for (int i = 0; i < 8; i++)
#pragma unroll
                for (int j = 0; j < 4; j++)
                    fma2(acc2[i][j], aa2[i], bb2[j]);
        }
        __syncthreads();
    }

#pragma unroll
    for (int i = 0; i < 8; i++) {
        int row = bm + ((i < 4) ? (ty * 4 + i) : (64 + ty * 4 + i - 4));
        float* cp = C + (size_t)row * NR + bn;
        float2 p0 = unpack2(acc2[i][0]);
        float2 p1 = unpack2(acc2[i][1]);
        float2 p2 = unpack2(acc2[i][2]);
        float2 p3 = unpack2(acc2[i][3]);
        *(float4*)(cp + (tx << 2))      = make_float4(p0.x, p0.y, p1.x, p1.y);
        *(float4*)(cp + 64 + (tx << 2)) = make_float4(p2.x, p2.y, p3.x, p3.y);
    }
}

// ---------------------------------------------------------------------------
extern "C" void kernel_launch(void* const* d_in, const int* in_sizes, int n_in,
                              void* d_out, int out_size)
{
    const float* x  = (const float*)d_in[0];
    const float* y  = (const float*)d_in[1];
    const float* W1 = (const float*)d_in[2];
    const float* b1 = (const float*)d_in[3];
    const float* W2 = (const float*)d_in[4];
    const float* b2 = (const float*)d_in[5];
    const float* W3 = (const float*)d_in[6];
    const float* b3 = (const float*)d_in[7];
    float* out = (float*)d_out;

    float *H1, *H2, *Z;
    cudaGetSymbolAddress((void**)&H1, g_H1);
    cudaGetSymbolAddress((void**)&H2, g_H2);
    cudaGetSymbolAddress((void**)&Z,  g_Z);

    // Layer 1: relu(x@W1+b1), relu(y@W1+b1) -> H1 [16384, 512]
    dim3 g1(HID / 128, NR / 128);
    gemm_bias_act<true><<<g1, 256>>>(x, W1, b1, H1, DIM, HID);
    gemm_bias_act<true><<<g1, 256>>>(y, W1, b1, H1 + (size_t)NR * HID, DIM, HID);

    // Layer 2: relu(H1@W2+b2) -> H2 [16384, 512]
    dim3 g2(HID / 128, 2 * NR / 128);
    gemm_bias_act<true><<<g2, 256>>>(H1, W2, b2, H2, HID, HID);

    // Layer 3 + L2 normalize: Z = l2norm(H2@W3+b3) [16384, 128]
    gemm_last_norm<<<2 * NR / 64, 256>>>(H2, W3, b3, Z, HID);

    // Similarity: out = Zx @ Zy^T  (TEMP = 1.0)
    dim3 g4(NR / 128, NR / 128);
    gemm_nt<<<g4, 256>>>(Z, Z + (size_t)NR * LAT, out);
}

// round 4
// speedup vs baseline: 1.1719x; 1.0888x over previous
#include <cuda_runtime.h>
#include <cuda_bf16.h>
#include <math.h>
#include <cstdint>

#define NR   8192
#define DIM  64
#define HID  512
#define LAT  128

// Scratch (device globals — allocation-free per harness rules)
__device__ float g_H1[2 * NR * HID];   // 32 MB
__device__ float g_H2[2 * NR * HID];   // 32 MB
__device__ float g_Z [2 * NR * LAT];   //  8 MB

// ===========================================================================
// f32x2 packed-FMA helpers (encoder SIMT kernels)
// ===========================================================================
__device__ __forceinline__ unsigned long long pack2_dup(float v) {
    unsigned long long r;
    unsigned u = __float_as_uint(v);
    asm("mov.b64 %0, {%1, %1};" : "=l"(r) : "r"(u));
    return r;
}
__device__ __forceinline__ void fma2(unsigned long long& d,
                                     unsigned long long a,
                                     unsigned long long b) {
    asm("fma.rn.f32x2 %0, %1, %2, %3;" : "=l"(d) : "l"(a), "l"(b), "l"(d));
}
__device__ __forceinline__ float2 unpack2(unsigned long long v) {
    unsigned lo, hi;
    asm("mov.b64 {%0, %1}, %2;" : "=r"(lo), "=r"(hi) : "l"(v));
    return make_float2(__uint_as_float(lo), __uint_as_float(hi));
}

__device__ __forceinline__ uint32_t smem_u32(const void* p) {
    uint32_t a;
    asm("{ .reg .u64 t; cvta.to.shared.u64 t, %1; cvt.u32.u64 %0, t; }"
        : "=r"(a) : "l"(p));
    return a;
}

// ===========================================================================
// mma.sync helpers (sm_80+ PTX — compiles on compute_103)
// ===========================================================================
__device__ __forceinline__ void ldmx4(uint32_t* r, uint32_t addr) {
    asm volatile("ldmatrix.sync.aligned.m8n8.x4.shared.b16 {%0,%1,%2,%3}, [%4];"
                 : "=r"(r[0]), "=r"(r[1]), "=r"(r[2]), "=r"(r[3]) : "r"(addr));
}
__device__ __forceinline__ void mma16816(float* d, const uint32_t* a,
                                         uint32_t b0, uint32_t b1) {
    asm volatile(
        "mma.sync.aligned.m16n8k16.row.col.f32.bf16.bf16.f32 "
        "{%0,%1,%2,%3}, {%4,%5,%6,%7}, {%8,%9}, {%0,%1,%2,%3};"
        : "+f"(d[0]), "+f"(d[1]), "+f"(d[2]), "+f"(d[3])
        : "r"(a[0]), "r"(a[1]), "r"(a[2]), "r"(a[3]), "r"(b0), "r"(b1));
}

// ===========================================================================
// Tensor-core NT GEMM: C[8192,8192] = ZA @ ZB^T, K=128, fp32 via bf16 hi/lo.
// One CTA per 128x128 tile; 256 threads (8 warps in 4x2 over M x N).
// smem tiles: 128 rows x 128 bf16, row stride 272 B (17x16B, ldmatrix
// conflict-free). Tiles: A_hi, A_lo, B_hi, B_lo.
// ===========================================================================
#define TSTRIDE   272
#define TILE_B    (128 * TSTRIDE)        // 34816
#define OFF_A_HI  0
#define OFF_A_LO  (TILE_B)
#define OFF_B_HI  (2 * TILE_B)
#define OFF_B_LO  (3 * TILE_B)
#define NT_SMEM   (4 * TILE_B)           // 139264 B

__global__ __launch_bounds__(256, 1) void gemm_nt_mma(
    const float* __restrict__ ZA, const float* __restrict__ ZB,
    float* __restrict__ C)
{
    extern __shared__ char smem[];
    const uint32_t sbase = smem_u32(smem);
    const int tid = threadIdx.x;
    const int bm = blockIdx.y << 7, bn = blockIdx.x << 7;

    // ---- load fp32 tiles, split to bf16 hi/lo, store to smem ----
    {
        const int row = tid >> 1;
        const int kb  = (tid & 1) << 6;   // 0 or 64
        const float* za = ZA + (size_t)(bm + row) * LAT + kb;
        const float* zb = ZB + (size_t)(bn + row) * LAT + kb;
#pragma unroll
        for (int c = 0; c < 8; c++) {
            const int kcol = kb + c * 8;
            const uint32_t off = (uint32_t)row * TSTRIDE + (uint32_t)kcol * 2;
#pragma unroll
            for (int s = 0; s < 2; s++) {
                const float* src = s ? zb : za;
                float4 f0 = *(const float4*)(src + c * 8);
                float4 f1 = *(const float4*)(src + c * 8 + 4);
                float f[8] = {f0.x,f0.y,f0.z,f0.w,f1.x,f1.y,f1.z,f1.w};
                uint32_t hw[4], lw[4];
#pragma unroll
                for (int j = 0; j < 4; j++) {
                    float a = f[2*j], b = f[2*j+1];
                    float ha = __bfloat162float(__float2bfloat16(a));
                    float hb = __bfloat162float(__float2bfloat16(b));
                    asm("cvt.rn.bf16x2.f32 %0, %1, %2;" : "=r"(hw[j]) : "f"(b), "f"(a));
                    float la = a - ha, lb = b - hb;
                    asm("cvt.rn.bf16x2.f32 %0, %1, %2;" : "=r"(lw[j]) : "f"(lb), "f"(la));
                }
                const int hi_off = s ? OFF_B_HI : OFF_A_HI;
                const int lo_off = s ? OFF_B_LO : OFF_A_LO;
                *(uint4*)(smem + hi_off + off) = make_uint4(hw[0],hw[1],hw[2],hw[3]);
                *(uint4*)(smem + lo_off + off) = make_uint4(lw[0],lw[1],lw[2],lw[3]);
            }
        }
    }
    __syncthreads();

    // ---- warp-level mma mainloop ----
    const int wid  = tid >> 5;
    const int lane = tid & 31;
    const int wm = (wid & 3) << 5;       // 0,32,64,96
    const int wn = (wid >> 2) << 6;      // 0,64

    float acc[2][8][4];
#pragma unroll
    for (int mt = 0; mt < 2; mt++)
#pragma unroll
        for (int nt = 0; nt < 8; nt++)
#pragma unroll
            for (int e = 0; e < 4; e++) acc[mt][nt][e] = 0.f;

    const int lrow  = lane & 15;
    const int khalf = lane >> 4;

#pragma unroll
    for (int ks = 0; ks < 8; ks++) {
        const uint32_t koff = (uint32_t)ks * 32 + (uint32_t)khalf * 16;

        uint32_t ah[2][4], al[2][4];
#pragma unroll
        for (int mt = 0; mt < 2; mt++) {
            const uint32_t ra = (uint32_t)(wm + mt * 16 + lrow) * TSTRIDE + koff;
            ldmx4(ah[mt], sbase + OFF_A_HI + ra);
            ldmx4(al[mt], sbase + OFF_A_LO + ra);
        }

        // B: 4 n-pairs, each ldmatrix.x4 -> frags for 2 n-tiles
        uint32_t bh[8][2], bl[8][2];
#pragma unroll
        for (int np = 0; np < 4; np++) {
            const uint32_t rb = (uint32_t)(wn + np * 16 + lrow) * TSTRIDE + koff;
            uint32_t th[4], tl[4];
            ldmx4(th, sbase + OFF_B_HI + rb);
            ldmx4(tl, sbase + OFF_B_LO + rb);
            bh[2*np+0][0] = th[0]; bh[2*np+0][1] = th[2];
            bh[2*np+1][0] = th[1]; bh[2*np+1][1] = th[3];
            bl[2*np+0][0] = tl[0]; bl[2*np+0][1] = tl[2];
            bl[2*np+1][0] = tl[1]; bl[2*np+1][1] = tl[3];
        }

        // D += Ah*Bh; D += Ah*Bl; D += Al*Bh (16 independent acc chains)
#pragma unroll
        for (int mt = 0; mt < 2; mt++)
#pragma unroll
            for (int nt = 0; nt < 8; nt++)
                mma16816(acc[mt][nt], ah[mt], bh[nt][0], bh[nt][1]);
#pragma unroll
        for (int mt = 0; mt < 2; mt++)
#pragma unroll
            for (int nt = 0; nt < 8; nt++)
                mma16816(acc[mt][nt], ah[mt], bl[nt][0], bl[nt][1]);
#pragma unroll
        for (int mt = 0; mt < 2; mt++)
#pragma unroll
            for (int nt = 0; nt < 8; nt++)
                mma16816(acc[mt][nt], al[mt], bh[nt][0], bh[nt][1]);
    }

    // ---- epilogue: direct coalesced float2 stores ----
    const int r0 = bm + wm + (lane >> 2);
    const int c0 = bn + wn + ((lane & 3) << 1);
#pragma unroll
    for (int mt = 0; mt < 2; mt++) {
#pragma unroll
        for (int nt = 0; nt < 8; nt++) {
            float* p0 = C + (size_t)(r0 + mt * 16)     * NR + c0 + nt * 8;
            float* p1 = C + (size_t)(r0 + mt * 16 + 8) * NR + c0 + nt * 8;
            *(float2*)p0 = make_float2(acc[mt][nt][0], acc[mt][nt][1]);
            *(float2*)p1 = make_float2(acc[mt][nt][2], acc[mt][nt][3]);
        }
    }
}

// ===========================================================================
// Encoder SIMT kernels (unchanged from round 2 — passing config)
// ===========================================================================
template<bool RELU>
__global__ __launch_bounds__(256) void gemm_bias_act(
    const float* __restrict__ A, const float* __restrict__ W,
    const float* __restrict__ bias, float* __restrict__ C,
    int K, int N)
{
    __shared__ float As[16][128];
    __shared__ float Bs[16][128];
    const int tid = threadIdx.x;
    const int tx = tid & 15, ty = tid >> 4;
    const int bm = blockIdx.y << 7, bn = blockIdx.x << 7;

    unsigned long long acc2[8][4];
#pragma unroll
    for (int i = 0; i < 8; i++)
#pragma unroll
        for (int j = 0; j < 4; j++) acc2[i][j] = 0ull;

    const int ar = tid >> 1;
    const int ak = (tid & 1) << 3;
    const int wk = ty;
    const int wn = tx << 3;

    for (int k0 = 0; k0 < K; k0 += 16) {
        const float* ap = A + (size_t)(bm + ar) * K + (k0 + ak);
        float4 v0 = *(const float4*)ap;
        float4 v1 = *(const float4*)(ap + 4);
        As[ak+0][ar] = v0.x; As[ak+1][ar] = v0.y; As[ak+2][ar] = v0.z; As[ak+3][ar] = v0.w;
        As[ak+4][ar] = v1.x; As[ak+5][ar] = v1.y; As[ak+6][ar] = v1.z; As[ak+7][ar] = v1.w;

        const float* wp = W + (size_t)(k0 + wk) * N + (bn + wn);
        *(float4*)&Bs[wk][wn]     = *(const float4*)wp;
        *(float4*)&Bs[wk][wn + 4] = *(const float4*)(wp + 4);
        __syncthreads();

#pragma unroll
        for (int kk = 0; kk < 16; kk++) {
            float4 a0 = *(const float4*)&As[kk][(ty << 2)];
            float4 a1 = *(const float4*)&As[kk][64 + (ty << 2)];
            unsigned long long aa2[8];
            aa2[0] = pack2_dup(a0.x); aa2[1] = pack2_dup(a0.y);
            aa2[2] = pack2_dup(a0.z); aa2[3] = pack2_dup(a0.w);
            aa2[4] = pack2_dup(a1.x); aa2[5] = pack2_dup(a1.y);
            aa2[6] = pack2_dup(a1.z); aa2[7] = pack2_dup(a1.w);
            ulonglong2 q0 = *(const ulonglong2*)&Bs[kk][(tx << 2)];
            ulonglong2 q1 = *(const ulonglong2*)&Bs[kk][64 + (tx << 2)];
            unsigned long long bb2[4] = {q0.x, q0.y, q1.x, q1.y};
#pragma unroll
            for (int i = 0; i < 8; i++)
#pragma unroll
                for (int j = 0; j < 4; j++)
                    fma2(acc2[i][j], aa2[i], bb2[j]);
        }
        __syncthreads();
    }

    float4 bv0 = *(const float4*)&bias[bn + (tx << 2)];
    float4 bv1 = *(const float4*)&bias[bn + 64 + (tx << 2)];
    float bb[8] = {bv0.x,bv0.y,bv0.z,bv0.w,bv1.x,bv1.y,bv1.z,bv1.w};
#pragma unroll
    for (int i = 0; i < 8; i++) {
        int row = bm + ((i < 4) ? (ty * 4 + i) : (64 + ty * 4 + i - 4));
        float o[8];
#pragma unroll
        for (int j = 0; j < 4; j++) {
            float2 p = unpack2(acc2[i][j]);
            o[2*j+0] = p.x + bb[2*j+0];
            o[2*j+1] = p.y + bb[2*j+1];
        }
        if (RELU) {
#pragma unroll
            for (int j = 0; j < 8; j++) o[j] = fmaxf(o[j], 0.f);
        }
        float* cp = C + (size_t)row * N + bn;
        *(float4*)(cp + (tx << 2))      = make_float4(o[0], o[1], o[2], o[3]);
        *(float4*)(cp + 64 + (tx << 2)) = make_float4(o[4], o[5], o[6], o[7]);
    }
}

__global__ __launch_bounds__(256) void gemm_last_norm(
    const float* __restrict__ A, const float* __restrict__ W,
    const float* __restrict__ bias, float* __restrict__ Z, int K)
{
    const int N = LAT;
    __shared__ float As[16][64];
    __shared__ float Bs[16][128];
    __shared__ float red[64][17];
    const int tid = threadIdx.x;
    const int tx = tid & 15, ty = tid >> 4;
    const int bm = blockIdx.x << 6;

    unsigned long long acc2[4][4];
#pragma unroll
    for (int i = 0; i < 4; i++)
#pragma unroll
        for (int j = 0; j < 4; j++) acc2[i][j] = 0ull;

    const int ar = tid >> 2;
    const int ak = (tid & 3) << 2;
    const int wk = ty;
    const int wn = tx << 3;

    for (int k0 = 0; k0 < K; k0 += 16) {
        const float* ap = A + (size_t)(bm + ar) * K + (k0 + ak);
        float4 v0 = *(const float4*)ap;
        As[ak+0][ar] = v0.x; As[ak+1][ar] = v0.y; As[ak+2][ar] = v0.z; As[ak+3][ar] = v0.w;

        const float* wp = W + (size_t)(k0 + wk) * N + wn;
        *(float4*)&Bs[wk][wn]     = *(const float4*)wp;
        *(float4*)&Bs[wk][wn + 4] = *(const float4*)(wp + 4);
        __syncthreads();

#pragma unroll
        for (int kk = 0; kk < 16; kk++) {
            float4 a0 = *(const float4*)&As[kk][(ty << 2)];
            unsigned long long aa2[4];
            aa2[0] = pack2_dup(a0.x); aa2[1] = pack2_dup(a0.y);
            aa2[2] = pack2_dup(a0.z); aa2[3] = pack2_dup(a0.w);
            ulonglong2 q0 = *(const ulonglong2*)&Bs[kk][(tx << 2)];
            ulonglong2 q1 = *(const ulonglong2*)&Bs[kk][64 + (tx << 2)];
            unsigned long long bb2[4] = {q0.x, q0.y, q1.x, q1.y};
#pragma unroll
            for (int i = 0; i < 4; i++)
#pragma unroll
                for (int j = 0; j < 4; j++)
                    fma2(acc2[i][j], aa2[i], bb2[j]);
        }
        __syncthreads();
    }

    float4 bv0 = *(const float4*)&bias[(tx << 2)];
    float4 bv1 = *(const float4*)&bias[64 + (tx << 2)];
    float bb[8] = {bv0.x,bv0.y,bv0.z,bv0.w,bv1.x,bv1.y,bv1.z,bv1.w};

    float o[4][8];
#pragma unroll
    for (int i = 0; i < 4; i++) {
        float s = 0.f;
#pragma unroll
        for (int j = 0; j < 4; j++) {
            float2 p = unpack2(acc2[i][j]);
            o[i][2*j+0] = p.x + bb[2*j+0];
            o[i][2*j+1] = p.y + bb[2*j+1];
        }
#pragma unroll
        for (int j = 0; j < 8; j++) s = fmaf(o[i][j], o[i][j], s);
        red[ty * 4 + i][tx] = s;
    }
    __syncthreads();

    if (tid < 64) {
        float s = 0.f;
#pragma unroll
        for (int t = 0; t < 16; t++) s += red[tid][t];
        red[tid][16] = 1.f / fmaxf(sqrtf(s), 1e-12f);
    }
    __syncthreads();

#pragma unroll
    for (int i = 0; i < 4; i++) {
        int rl = ty * 4 + i;
        float inv = red[rl][16];
        float* zp = Z + (size_t)(bm + rl) * N;
        *(float4*)(zp + (tx << 2)) =
            make_float4(o[i][0]*inv, o[i][1]*inv, o[i][2]*inv, o[i][3]*inv);
        *(float4*)(zp + 64 + (tx << 2)) =
            make_float4(o[i][4]*inv, o[i][5]*inv, o[i][6]*inv, o[i][7]*inv);
    }
}

// ===========================================================================
extern "C" void kernel_launch(void* const* d_in, const int* in_sizes, int n_in,
                              void* d_out, int out_size)
{
    const float* x  = (const float*)d_in[0];
    const float* y  = (const float*)d_in[1];
    const float* W1 = (const float*)d_in[2];
    const float* b1 = (const float*)d_in[3];
    const float* W2 = (const float*)d_in[4];
    const float* b2 = (const float*)d_in[5];
    const float* W3 = (const float*)d_in[6];
    const float* b3 = (const float*)d_in[7];
    float* out = (float*)d_out;

    float *H1, *H2, *Z;
    cudaGetSymbolAddress((void**)&H1, g_H1);
    cudaGetSymbolAddress((void**)&H2, g_H2);
    cudaGetSymbolAddress((void**)&Z,  g_Z);

    cudaFuncSetAttribute(gemm_nt_mma, cudaFuncAttributeMaxDynamicSharedMemorySize, NT_SMEM);

    dim3 g1(HID / 128, NR / 128);
    gemm_bias_act<true><<<g1, 256>>>(x, W1, b1, H1, DIM, HID);
    gemm_bias_act<true><<<g1, 256>>>(y, W1, b1, H1 + (size_t)NR * HID, DIM, HID);

    dim3 g2(HID / 128, 2 * NR / 128);
    gemm_bias_act<true><<<g2, 256>>>(H1, W2, b2, H2, HID, HID);

    gemm_last_norm<<<2 * NR / 64, 256>>>(H2, W3, b3, Z, HID);

    dim3 g4(NR / 128, NR / 128);
    gemm_nt_mma<<<g4, 256, NT_SMEM>>>(Z, Z + (size_t)NR * LAT, out);
}

// round 5
// speedup vs baseline: 1.3678x; 1.1671x over previous
#include <cuda_runtime.h>
#include <cuda_bf16.h>
#include <math.h>
#include <cstdint>

#define NR   8192
#define DIM  64
#define HID  512
#define LAT  128

// Scratch (device globals — allocation-free per harness rules)
__device__ float g_H1[2 * NR * HID];   // 32 MB
__device__ float g_H2[2 * NR * HID];   // 32 MB
__device__ float g_Z [2 * NR * LAT];   //  8 MB
// Transposed + hi/lo-split weights (bf16)
__device__ __nv_bfloat16 g_WT1h[HID * DIM], g_WT1l[HID * DIM];   // [512,64]
__device__ __nv_bfloat16 g_WT2h[HID * HID], g_WT2l[HID * HID];   // [512,512]
__device__ __nv_bfloat16 g_WT3h[LAT * HID], g_WT3l[LAT * HID];   // [128,512]

// ===========================================================================
// helpers
// ===========================================================================
__device__ __forceinline__ uint32_t smem_u32(const void* p) {
    uint32_t a;
    asm("{ .reg .u64 t; cvta.to.shared.u64 t, %1; cvt.u32.u64 %0, t; }"
        : "=r"(a) : "l"(p));
    return a;
}
__device__ __forceinline__ void ldmx4(uint32_t* r, uint32_t addr) {
    asm volatile("ldmatrix.sync.aligned.m8n8.x4.shared.b16 {%0,%1,%2,%3}, [%4];"
                 : "=r"(r[0]), "=r"(r[1]), "=r"(r[2]), "=r"(r[3]) : "r"(addr));
}
__device__ __forceinline__ void mma16816(float* d, const uint32_t* a,
                                         uint32_t b0, uint32_t b1) {
    asm volatile(
        "mma.sync.aligned.m16n8k16.row.col.f32.bf16.bf16.f32 "
        "{%0,%1,%2,%3}, {%4,%5,%6,%7}, {%8,%9}, {%0,%1,%2,%3};"
        : "+f"(d[0]), "+f"(d[1]), "+f"(d[2]), "+f"(d[3])
        : "r"(a[0]), "r"(a[1]), "r"(a[2]), "r"(a[3]), "r"(b0), "r"(b1));
}
// split 8 fp32 -> bf16 hi (uint4) + bf16 lo (uint4)
__device__ __forceinline__ void split8(const float* f, uint4& hv, uint4& lv) {
    uint32_t hw[4], lw[4];
#pragma unroll
    for (int j = 0; j < 4; j++) {
        float a = f[2*j], b = f[2*j+1];
        float ha = __bfloat162float(__float2bfloat16(a));
        float hb = __bfloat162float(__float2bfloat16(b));
        asm("cvt.rn.bf16x2.f32 %0, %1, %2;" : "=r"(hw[j]) : "f"(b), "f"(a));
        float la = a - ha, lb = b - hb;
        asm("cvt.rn.bf16x2.f32 %0, %1, %2;" : "=r"(lw[j]) : "f"(lb), "f"(la));
    }
    hv = make_uint4(hw[0], hw[1], hw[2], hw[3]);
    lv = make_uint4(lw[0], lw[1], lw[2], lw[3]);
}

// ===========================================================================
// prep: WT[n*K+k] = hi/lo bf16 split of W[k*N+n]
// ===========================================================================
__global__ void prep_wt(const float* __restrict__ W,
                        __nv_bfloat16* __restrict__ WTh,
                        __nv_bfloat16* __restrict__ WTl, int K, int N) {
    int idx = blockIdx.x * blockDim.x + threadIdx.x;
    if (idx >= K * N) return;
    int n = idx / K, k = idx - n * K;
    float v = W[(size_t)k * N + n];
    __nv_bfloat16 h = __float2bfloat16(v);
    WTh[idx] = h;
    WTl[idx] = __float2bfloat16(v - __bfloat162float(h));
}

// ===========================================================================
// Encoder NT mma GEMM: C[M,Ntot] = epi(A[M,K] @ WT[Ntot,K]^T + bias)
// CTA tile 128x128, BK=64 chunks, 8 warps (4x2), 3-pass bf16 hi/lo.
// EPI: false -> bias+ReLU (fp32 C); true -> bias + row L2 norm (Ntot==128).
// ===========================================================================
#define STR2      144                    // 9*16B: ldmatrix conflict-free
#define T2_BYTES  (128 * STR2)           // 18432
#define E_A_HI    0
#define E_A_LO    (T2_BYTES)
#define E_B_HI    (2 * T2_BYTES)
#define E_B_LO    (3 * T2_BYTES)
#define ENC_SMEM  (4 * T2_BYTES)         // 73728 B

template<int K, bool NORM>
__global__ __launch_bounds__(256, 1) void gemm_enc(
    const float* __restrict__ A,
    const __nv_bfloat16* __restrict__ Bh, const __nv_bfloat16* __restrict__ Bl,
    const float* __restrict__ bias, float* __restrict__ C, int Ntot)
{
    extern __shared__ char smem[];
    const uint32_t sbase = smem_u32(smem);
    const int tid = threadIdx.x;
    const int bm = blockIdx.y << 7, bn = blockIdx.x << 7;
    const int wid = tid >> 5, lane = tid & 31;
    const int wm = (wid & 3) << 5, wn = (wid >> 2) << 6;
    const int lrow = lane & 15, khalf = lane >> 4;

    float acc[2][8][4];
#pragma unroll
    for (int mt = 0; mt < 2; mt++)
#pragma unroll
        for (int nt = 0; nt < 8; nt++)
#pragma unroll
            for (int e = 0; e < 4; e++) acc[mt][nt][e] = 0.f;

    const int lr  = tid >> 1;            // 0..127 (tile row for loads)
    const int ksg = (tid & 1) << 5;      // 0 or 32 (k elements)

    for (int k0 = 0; k0 < K; k0 += 64) {
        // A chunk: fp32 -> bf16 hi/lo
        {
            const float* ap = A + (size_t)(bm + lr) * K + k0 + ksg;
            const uint32_t ob = (uint32_t)lr * STR2 + (uint32_t)ksg * 2;
#pragma unroll
            for (int c = 0; c < 4; c++) {
                float4 f0 = *(const float4*)(ap + c * 8);
                float4 f1 = *(const float4*)(ap + c * 8 + 4);
                float f[8] = {f0.x,f0.y,f0.z,f0.w,f1.x,f1.y,f1.z,f1.w};
                uint4 hv, lv;
                split8(f, hv, lv);
                *(uint4*)(smem + E_A_HI + ob + c * 16) = hv;
                *(uint4*)(smem + E_A_LO + ob + c * 16) = lv;
            }
        }
        // B chunk: straight bf16 copies
        {
            const char* bph = (const char*)(Bh + (size_t)(bn + lr) * K + k0 + ksg);
            const char* bpl = (const char*)(Bl + (size_t)(bn + lr) * K + k0 + ksg);
            const uint32_t ob = (uint32_t)lr * STR2 + (uint32_t)ksg * 2;
#pragma unroll
            for (int c = 0; c < 4; c++) {
                *(uint4*)(smem + E_B_HI + ob + c * 16) = *(const uint4*)(bph + c * 16);
                *(uint4*)(smem + E_B_LO + ob + c * 16) = *(const uint4*)(bpl + c * 16);
            }
        }
        __syncthreads();

#pragma unroll
        for (int ks = 0; ks < 4; ks++) {
            const uint32_t koff = (uint32_t)ks * 32 + (uint32_t)khalf * 16;
            uint32_t ah[2][4], al[2][4];
#pragma unroll
            for (int mt = 0; mt < 2; mt++) {
                const uint32_t ra = (uint32_t)(wm + mt * 16 + lrow) * STR2 + koff;
                ldmx4(ah[mt], sbase + E_A_HI + ra);
                ldmx4(al[mt], sbase + E_A_LO + ra);
            }
            uint32_t bhf[8][2], blf[8][2];
#pragma unroll
            for (int np = 0; np < 4; np++) {
                const uint32_t rb = (uint32_t)(wn + np * 16 + lrow) * STR2 + koff;
                uint32_t th[4], tl[4];
                ldmx4(th, sbase + E_B_HI + rb);
                ldmx4(tl, sbase + E_B_LO + rb);
                bhf[2*np+0][0] = th[0]; bhf[2*np+0][1] = th[2];
                bhf[2*np+1][0] = th[1]; bhf[2*np+1][1] = th[3];
                blf[2*np+0][0] = tl[0]; blf[2*np+0][1] = tl[2];
                blf[2*np+1][0] = tl[1]; blf[2*np+1][1] = tl[3];
            }
#pragma unroll
            for (int mt = 0; mt < 2; mt++)
#pragma unroll
                for (int nt = 0; nt < 8; nt++)
                    mma16816(acc[mt][nt], ah[mt], bhf[nt][0], bhf[nt][1]);
#pragma unroll
            for (int mt = 0; mt < 2; mt++)
#pragma unroll
                for (int nt = 0; nt < 8; nt++)
                    mma16816(acc[mt][nt], ah[mt], blf[nt][0], blf[nt][1]);
#pragma unroll
            for (int mt = 0; mt < 2; mt++)
#pragma unroll
                for (int nt = 0; nt < 8; nt++)
                    mma16816(acc[mt][nt], al[mt], bhf[nt][0], bhf[nt][1]);
        }
        __syncthreads();
    }

    const int r_in = lane >> 2;          // 0..7
    const int c_in = (lane & 3) << 1;    // 0,2,4,6

    float bias2[8][2];
#pragma unroll
    for (int nt = 0; nt < 8; nt++) {
        bias2[nt][0] = bias[bn + wn + nt * 8 + c_in];
        bias2[nt][1] = bias[bn + wn + nt * 8 + c_in + 1];
    }

    if (!NORM) {
        // bias + ReLU, fp32 store
#pragma unroll
        for (int mt = 0; mt < 2; mt++) {
            const int r0 = bm + wm + mt * 16 + r_in;
#pragma unroll
            for (int nt = 0; nt < 8; nt++) {
                float o0 = fmaxf(acc[mt][nt][0] + bias2[nt][0], 0.f);
                float o1 = fmaxf(acc[mt][nt][1] + bias2[nt][1], 0.f);
                float o2 = fmaxf(acc[mt][nt][2] + bias2[nt][0], 0.f);
                float o3 = fmaxf(acc[mt][nt][3] + bias2[nt][1], 0.f);
                const int col = bn + wn + nt * 8 + c_in;
                *(float2*)(C + (size_t)r0 * Ntot + col)       = make_float2(o0, o1);
                *(float2*)(C + (size_t)(r0 + 8) * Ntot + col) = make_float2(o2, o3);
            }
        }
    } else {
        // bias + row L2 normalize (Ntot == 128, gridDim.x == 1)
        float ss[2][2];
#pragma unroll
        for (int mt = 0; mt < 2; mt++) { ss[mt][0] = 0.f; ss[mt][1] = 0.f; }
#pragma unroll
        for (int mt = 0; mt < 2; mt++)
#pragma unroll
            for (int nt = 0; nt < 8; nt++) {
                acc[mt][nt][0] += bias2[nt][0];
                acc[mt][nt][1] += bias2[nt][1];
                acc[mt][nt][2] += bias2[nt][0];
                acc[mt][nt][3] += bias2[nt][1];
                ss[mt][0] = fmaf(acc[mt][nt][0], acc[mt][nt][0],
                            fmaf(acc[mt][nt][1], acc[mt][nt][1], ss[mt][0]));
                ss[mt][1] = fmaf(acc[mt][nt][2], acc[mt][nt][2],
                            fmaf(acc[mt][nt][3], acc[mt][nt][3], ss[mt][1]));
            }
        // reduce over the 4 lanes of each row quad
#pragma unroll
        for (int m = 1; m <= 2; m <<= 1) {
#pragma unroll
            for (int mt = 0; mt < 2; mt++) {
                ss[mt][0] += __shfl_xor_sync(0xFFFFFFFFu, ss[mt][0], m);
                ss[mt][1] += __shfl_xor_sync(0xFFFFFFFFu, ss[mt][1], m);
            }
        }
        float* red = (float*)smem;          // [128][2]
        float* invp = red + 256;            // [128]
        const int half = wid >> 2;
        if ((lane & 3) == 0) {
#pragma unroll
            for (int mt = 0; mt < 2; mt++) {
                red[(wm + mt * 16 + r_in) * 2 + half]     = ss[mt][0];
                red[(wm + mt * 16 + r_in + 8) * 2 + half] = ss[mt][1];
            }
        }
        __syncthreads();
        if (tid < 128) {
            float s = red[tid * 2] + red[tid * 2 + 1];
            invp[tid] = 1.f / fmaxf(sqrtf(s), 1e-12f);
        }
        __syncthreads();
#pragma unroll
        for (int mt = 0; mt < 2; mt++) {
            const int rl = wm + mt * 16 + r_in;
            const float inv0 = invp[rl], inv1 = invp[rl + 8];
            const int r0 = bm + rl;
#pragma unroll
            for (int nt = 0; nt < 8; nt++) {
                const int col = wn + nt * 8 + c_in;
                *(float2*)(C + (size_t)r0 * Ntot + col) =
                    make_float2(acc[mt][nt][0] * inv0, acc[mt][nt][1] * inv0);
                *(float2*)(C + (size_t)(r0 + 8) * Ntot + col) =
                    make_float2(acc[mt][nt][2] * inv1, acc[mt][nt][3] * inv1);
            }
        }
    }
}

// ===========================================================================
// Final NT GEMM: C[8192,8192] = ZA @ ZB^T, K=128 (unchanged, validated)
// ===========================================================================
#define TSTRIDE   272
#define TILE_B    (128 * TSTRIDE)
#define OFF_A_HI  0
#define OFF_A_LO  (TILE_B)
#define OFF_B_HI  (2 * TILE_B)
#define OFF_B_LO  (3 * TILE_B)
#define NT_SMEM   (4 * TILE_B)           // 139264 B

__global__ __launch_bounds__(256, 1) void gemm_nt_mma(
    const float* __restrict__ ZA, const float* __restrict__ ZB,
    float* __restrict__ C)
{
    extern __shared__ char smem[];
    const uint32_t sbase = smem_u32(smem);
    const int tid = threadIdx.x;
    const int bm = blockIdx.y << 7, bn = blockIdx.x << 7;

    {
        const int row = tid >> 1;
        const int kb  = (tid & 1) << 6;
        const float* za = ZA + (size_t)(bm + row) * LAT + kb;
        const float* zb = ZB + (size_t)(bn + row) * LAT + kb;
#pragma unroll
        for (int c = 0; c < 8; c++) {
            const int kcol = kb + c * 8;
            const uint32_t off = (uint32_t)row * TSTRIDE + (uint32_t)kcol * 2;
#pragma unroll
            for (int s = 0; s < 2; s++) {
                const float* src = s ? zb : za;
                float4 f0 = *(const float4*)(src + c * 8);
                float4 f1 = *(const float4*)(src + c * 8 + 4);
                float f[8] = {f0.x,f0.y,f0.z,f0.w,f1.x,f1.y,f1.z,f1.w};
                uint4 hv, lv;
                split8(f, hv, lv);
                const int hi_off = s ? OFF_B_HI : OFF_A_HI;
                const int lo_off = s ? OFF_B_LO : OFF_A_LO;
                *(uint4*)(smem + hi_off + off) = hv;
                *(uint4*)(smem + lo_off + off) = lv;
            }
        }
    }
    __syncthreads();

    const int wid  = tid >> 5;
    const int lane = tid & 31;
    const int wm = (wid & 3) << 5;
    const int wn = (wid >> 2) << 6;

    float acc[2][8][4];
#pragma unroll
    for (int mt = 0; mt < 2; mt++)
#pragma unroll
        for (int nt = 0; nt < 8; nt++)
#pragma unroll
            for (int e = 0; e < 4; e++) acc[mt][nt][e] = 0.f;

    const int lrow  = lane & 15;
    const int khalf = lane >> 4;

#pragma unroll
    for (int ks = 0; ks < 8; ks++) {
        const uint32_t koff = (uint32_t)ks * 32 + (uint32_t)khalf * 16;

        uint32_t ah[2][4], al[2][4];
#pragma unroll
        for (int mt = 0; mt < 2; mt++) {
            const uint32_t ra = (uint32_t)(wm + mt * 16 + lrow) * TSTRIDE + koff;
            ldmx4(ah[mt], sbase + OFF_A_HI + ra);
            ldmx4(al[mt], sbase + OFF_A_LO + ra);
        }
        uint32_t bh[8][2], bl[8][2];
#pragma unroll
        for (int np = 0; np < 4; np++) {
            const uint32_t rb = (uint32_t)(wn + np * 16 + lrow) * TSTRIDE + koff;
            uint32_t th[4], tl[4];
            ldmx4(th, sbase + OFF_B_HI + rb);
            ldmx4(tl, sbase + OFF_B_LO + rb);
            bh[2*np+0][0] = th[0]; bh[2*np+0][1] = th[2];
            bh[2*np+1][0] = th[1]; bh[2*np+1][1] = th[3];
            bl[2*np+0][0] = tl[0]; bl[2*np+0][1] = tl[2];
            bl[2*np+1][0] = tl[1]; bl[2*np+1][1] = tl[3];
        }
#pragma unroll
        for (int mt = 0; mt < 2; mt++)
#pragma unroll
            for (int nt = 0; nt < 8; nt++)
                mma16816(acc[mt][nt], ah[mt], bh[nt][0], bh[nt][1]);
#pragma unroll
        for (int mt = 0; mt < 2; mt++)
#pragma unroll
            for (int nt = 0; nt < 8; nt++)
                mma16816(acc[mt][nt], ah[mt], bl[nt][0], bl[nt][1]);
#pragma unroll
        for (int mt = 0; mt < 2; mt++)
#pragma unroll
            for (int nt = 0; nt < 8; nt++)
                mma16816(acc[mt][nt], al[mt], bh[nt][0], bh[nt][1]);
    }

    const int r0 = bm + wm + (lane >> 2);
    const int c0 = bn + wn + ((lane & 3) << 1);
#pragma unroll
    for (int mt = 0; mt < 2; mt++) {
#pragma unroll
        for (int nt = 0; nt < 8; nt++) {
            float* p0 = C + (size_t)(r0 + mt * 16)     * NR + c0 + nt * 8;
            float* p1 = C + (size_t)(r0 + mt * 16 + 8) * NR + c0 + nt * 8;
            *(float2*)p0 = make_float2(acc[mt][nt][0], acc[mt][nt][1]);
            *(float2*)p1 = make_float2(acc[mt][nt][2], acc[mt][nt][3]);
        }
    }
}

// ===========================================================================
extern "C" void kernel_launch(void* const* d_in, const int* in_sizes, int n_in,
                              void* d_out, int out_size)
{
    const float* x  = (const float*)d_in[0];
    const float* y  = (const float*)d_in[1];
    const float* W1 = (const float*)d_in[2];
    const float* b1 = (const float*)d_in[3];
    const float* W2 = (const float*)d_in[4];
    const float* b2 = (const float*)d_in[5];
    const float* W3 = (const float*)d_in[6];
    const float* b3 = (const float*)d_in[7];
    float* out = (float*)d_out;

    float *H1, *H2, *Z;
    cudaGetSymbolAddress((void**)&H1, g_H1);
    cudaGetSymbolAddress((void**)&H2, g_H2);
    cudaGetSymbolAddress((void**)&Z,  g_Z);
    __nv_bfloat16 *WT1h, *WT1l, *WT2h, *WT2l, *WT3h, *WT3l;
    cudaGetSymbolAddress((void**)&WT1h, g_WT1h);
    cudaGetSymbolAddress((void**)&WT1l, g_WT1l);
    cudaGetSymbolAddress((void**)&WT2h, g_WT2h);
    cudaGetSymbolAddress((void**)&WT2l, g_WT2l);
    cudaGetSymbolAddress((void**)&WT3h, g_WT3h);
    cudaGetSymbolAddress((void**)&WT3l, g_WT3l);

    cudaFuncSetAttribute(gemm_nt_mma, cudaFuncAttributeMaxDynamicSharedMemorySize, NT_SMEM);
    cudaFuncSetAttribute(gemm_enc<64, false>,  cudaFuncAttributeMaxDynamicSharedMemorySize, ENC_SMEM);
    cudaFuncSetAttribute(gemm_enc<512, false>, cudaFuncAttributeMaxDynamicSharedMemorySize, ENC_SMEM);
    cudaFuncSetAttribute(gemm_enc<512, true>,  cudaFuncAttributeMaxDynamicSharedMemorySize, ENC_SMEM);

    // weight transpose + hi/lo split
    prep_wt<<<(DIM * HID + 255) / 256, 256>>>(W1, WT1h, WT1l, DIM, HID);
    prep_wt<<<(HID * HID + 255) / 256, 256>>>(W2, WT2h, WT2l, HID, HID);
    prep_wt<<<(HID * LAT + 255) / 256, 256>>>(W3, WT3h, WT3l, HID, LAT);

    // Layer 1
    dim3 g1(HID / 128, NR / 128);
    gemm_enc<64, false><<<g1, 256, ENC_SMEM>>>(x, WT1h, WT1l, b1, H1, HID);
    gemm_enc<64, false><<<g1, 256, ENC_SMEM>>>(y, WT1h, WT1l, b1, H1 + (size_t)NR * HID, HID);

    // Layer 2
    dim3 g2(HID / 128, 2 * NR / 128);
    gemm_enc<512, false><<<g2, 256, ENC_SMEM>>>(H1, WT2h, WT2l, b2, H2, HID);

    // Layer 3 + L2 normalize
    dim3 g3(1, 2 * NR / 128);
    gemm_enc<512, true><<<g3, 256, ENC_SMEM>>>(H2, WT3h, WT3l, b3, Z, LAT);

    // Similarity
    dim3 g4(NR / 128, NR / 128);
    gemm_nt_mma<<<g4, 256, NT_SMEM>>>(Z, Z + (size_t)NR * LAT, out);
}

// round 6
// speedup vs baseline: 1.5988x; 1.1689x over previous
#include <cuda_runtime.h>
#include <cuda_bf16.h>
#include <math.h>
#include <cstdint>

#define NR   8192
#define DIM  64
#define HID  512
#define LAT  128

// Scratch (device globals — allocation-free per harness rules)
__device__ __nv_bfloat16 g_H1h[2 * NR * HID], g_H1l[2 * NR * HID];  // 16MB each
__device__ __nv_bfloat16 g_H2h[2 * NR * HID], g_H2l[2 * NR * HID];
__device__ __nv_bfloat16 g_Zh [2 * NR * LAT], g_Zl [2 * NR * LAT];  // 4MB each
__device__ __nv_bfloat16 g_WT1h[HID * DIM], g_WT1l[HID * DIM];
__device__ __nv_bfloat16 g_WT2h[HID * HID], g_WT2l[HID * HID];
__device__ __nv_bfloat16 g_WT3h[LAT * HID], g_WT3l[LAT * HID];

// ===========================================================================
// helpers
// ===========================================================================
__device__ __forceinline__ uint32_t smem_u32(const void* p) {
    uint32_t a;
    asm("{ .reg .u64 t; cvta.to.shared.u64 t, %1; cvt.u32.u64 %0, t; }"
        : "=r"(a) : "l"(p));
    return a;
}
__device__ __forceinline__ void ldmx4(uint32_t* r, uint32_t addr) {
    asm volatile("ldmatrix.sync.aligned.m8n8.x4.shared.b16 {%0,%1,%2,%3}, [%4];"
                 : "=r"(r[0]), "=r"(r[1]), "=r"(r[2]), "=r"(r[3]) : "r"(addr));
}
__device__ __forceinline__ void mma16816(float* d, const uint32_t* a,
                                         uint32_t b0, uint32_t b1) {
    asm volatile(
        "mma.sync.aligned.m16n8k16.row.col.f32.bf16.bf16.f32 "
        "{%0,%1,%2,%3}, {%4,%5,%6,%7}, {%8,%9}, {%0,%1,%2,%3};"
        : "+f"(d[0]), "+f"(d[1]), "+f"(d[2]), "+f"(d[3])
        : "r"(a[0]), "r"(a[1]), "r"(a[2]), "r"(a[3]), "r"(b0), "r"(b1));
}
__device__ __forceinline__ void cpa16(uint32_t dst, const void* src) {
    asm volatile("cp.async.cg.shared.global [%0], [%1], 16;"
                 :: "r"(dst), "l"(src));
}
#define CP_COMMIT() asm volatile("cp.async.commit_group;")
#define CP_WAIT0()  asm volatile("cp.async.wait_group 0;" ::: "memory")

// split 8 fp32 -> bf16 hi (uint4) + lo (uint4)
__device__ __forceinline__ void split8(const float* f, uint4& hv, uint4& lv) {
    uint32_t hw[4], lw[4];
#pragma unroll
    for (int j = 0; j < 4; j++) {
        float a = f[2*j], b = f[2*j+1];
        float ha = __bfloat162float(__float2bfloat16(a));
        float hb = __bfloat162float(__float2bfloat16(b));
        asm("cvt.rn.bf16x2.f32 %0, %1, %2;" : "=r"(hw[j]) : "f"(b), "f"(a));
        float la = a - ha, lb = b - hb;
        asm("cvt.rn.bf16x2.f32 %0, %1, %2;" : "=r"(lw[j]) : "f"(lb), "f"(la));
    }
    hv = make_uint4(hw[0], hw[1], hw[2], hw[3]);
    lv = make_uint4(lw[0], lw[1], lw[2], lw[3]);
}
// split pair of fp32 -> packed bf16x2 hi + lo words
__device__ __forceinline__ void split2(float a, float b, uint32_t& h, uint32_t& l) {
    float ha = __bfloat162float(__float2bfloat16(a));
    float hb = __bfloat162float(__float2bfloat16(b));
    asm("cvt.rn.bf16x2.f32 %0, %1, %2;" : "=r"(h) : "f"(b), "f"(a));
    float la = a - ha, lb = b - hb;
    asm("cvt.rn.bf16x2.f32 %0, %1, %2;" : "=r"(l) : "f"(lb), "f"(la));
}

// ===========================================================================
// prep: WT[n*K+k] = hi/lo bf16 split of W[k*N+n]
// ===========================================================================
__global__ void prep_wt(const float* __restrict__ W,
                        __nv_bfloat16* __restrict__ WTh,
                        __nv_bfloat16* __restrict__ WTl, int K, int N) {
    int idx = blockIdx.x * blockDim.x + threadIdx.x;
    if (idx >= K * N) return;
    int n = idx / K, k = idx - n * K;
    float v = W[(size_t)k * N + n];
    __nv_bfloat16 h = __float2bfloat16(v);
    WTh[idx] = h;
    WTl[idx] = __float2bfloat16(v - __bfloat162float(h));
}

// ===========================================================================
// Encoder mma GEMM core. CTA tile 128x128, BK=64, 8 warps (4x2), 3-pass.
// A_BF16: A given as bf16 hi/lo arrays; else fp32 (split in-kernel).
// NORM:   bias + row L2 norm (Ntot==128) ; else bias + ReLU.
// Output: bf16 hi/lo arrays.
// ===========================================================================
#define STR2      144
#define T2_BYTES  (128 * STR2)           // 18432
#define E_A_HI    0
#define E_A_LO    (T2_BYTES)
#define E_B_HI    (2 * T2_BYTES)
#define E_B_LO    (3 * T2_BYTES)
#define ENC_SMEM  (4 * T2_BYTES)         // 73728 B

template<int K, bool A_BF16, bool NORM>
__global__ __launch_bounds__(256, 1) void gemm_enc(
    const void* __restrict__ A0, const void* __restrict__ A1,
    const __nv_bfloat16* __restrict__ Bh, const __nv_bfloat16* __restrict__ Bl,
    const float* __restrict__ bias,
    __nv_bfloat16* __restrict__ Ch, __nv_bfloat16* __restrict__ Cl, int Ntot)
{
    extern __shared__ char smem[];
    const uint32_t sbase = smem_u32(smem);
    const int tid = threadIdx.x;
    const int bm = blockIdx.y << 7, bn = blockIdx.x << 7;
    const int wid = tid >> 5, lane = tid & 31;
    const int wm = (wid & 3) << 5, wn = (wid >> 2) << 6;
    const int lrow = lane & 15, khalf = lane >> 4;

    float acc[2][8][4];
#pragma unroll
    for (int mt = 0; mt < 2; mt++)
#pragma unroll
        for (int nt = 0; nt < 8; nt++)
#pragma unroll
            for (int e = 0; e < 4; e++) acc[mt][nt][e] = 0.f;

    const int lr  = tid >> 1;
    const int ksg = (tid & 1) << 5;      // 0 or 32 k-elements

    for (int k0 = 0; k0 < K; k0 += 64) {
        const uint32_t ob = (uint32_t)lr * STR2 + (uint32_t)ksg * 2;
        if (A_BF16) {
            const __nv_bfloat16* ah = (const __nv_bfloat16*)A0 + (size_t)(bm + lr) * K + k0 + ksg;
            const __nv_bfloat16* al = (const __nv_bfloat16*)A1 + (size_t)(bm + lr) * K + k0 + ksg;
#pragma unroll
            for (int c = 0; c < 4; c++) {
                cpa16(sbase + E_A_HI + ob + c * 16, (const char*)ah + c * 16);
                cpa16(sbase + E_A_LO + ob + c * 16, (const char*)al + c * 16);
            }
        } else {
            const float* ap = (const float*)A0 + (size_t)(bm + lr) * K + k0 + ksg;
#pragma unroll
            for (int c = 0; c < 4; c++) {
                float4 f0 = *(const float4*)(ap + c * 8);
                float4 f1 = *(const float4*)(ap + c * 8 + 4);
                float f[8] = {f0.x,f0.y,f0.z,f0.w,f1.x,f1.y,f1.z,f1.w};
                uint4 hv, lv;
                split8(f, hv, lv);
                *(uint4*)(smem + E_A_HI + ob + c * 16) = hv;
                *(uint4*)(smem + E_A_LO + ob + c * 16) = lv;
            }
        }
        {
            const char* bph = (const char*)(Bh + (size_t)(bn + lr) * K + k0 + ksg);
            const char* bpl = (const char*)(Bl + (size_t)(bn + lr) * K + k0 + ksg);
#pragma unroll
            for (int c = 0; c < 4; c++) {
                cpa16(sbase + E_B_HI + ob + c * 16, bph + c * 16);
                cpa16(sbase + E_B_LO + ob + c * 16, bpl + c * 16);
            }
        }
        CP_COMMIT();
        CP_WAIT0();
        __syncthreads();

#pragma unroll
        for (int ks = 0; ks < 4; ks++) {
            const uint32_t koff = (uint32_t)ks * 32 + (uint32_t)khalf * 16;
            uint32_t ah[2][4], al[2][4];
#pragma unroll
            for (int mt = 0; mt < 2; mt++) {
                const uint32_t ra = (uint32_t)(wm + mt * 16 + lrow) * STR2 + koff;
                ldmx4(ah[mt], sbase + E_A_HI + ra);
                ldmx4(al[mt], sbase + E_A_LO + ra);
            }
#pragma unroll
            for (int np = 0; np < 4; np++) {
                const uint32_t rb = (uint32_t)(wn + np * 16 + lrow) * STR2 + koff;
                uint32_t th[4], tl[4];
                ldmx4(th, sbase + E_B_HI + rb);
                ldmx4(tl, sbase + E_B_LO + rb);
#pragma unroll
                for (int mt = 0; mt < 2; mt++) {
                    mma16816(acc[mt][2*np+0], ah[mt], th[0], th[2]);
                    mma16816(acc[mt][2*np+1], ah[mt], th[1], th[3]);
                }
#pragma unroll
                for (int mt = 0; mt < 2; mt++) {
                    mma16816(acc[mt][2*np+0], ah[mt], tl[0], tl[2]);
                    mma16816(acc[mt][2*np+1], ah[mt], tl[1], tl[3]);
                }
#pragma unroll
                for (int mt = 0; mt < 2; mt++) {
                    mma16816(acc[mt][2*np+0], al[mt], th[0], th[2]);
                    mma16816(acc[mt][2*np+1], al[mt], th[1], th[3]);
                }
            }
        }
        __syncthreads();
    }

    const int r_in = lane >> 2;
    const int c_in = (lane & 3) << 1;

    float bias2[8][2];
#pragma unroll
    for (int nt = 0; nt < 8; nt++) {
        bias2[nt][0] = bias[bn + wn + nt * 8 + c_in];
        bias2[nt][1] = bias[bn + wn + nt * 8 + c_in + 1];
    }

    if (!NORM) {
#pragma unroll
        for (int mt = 0; mt < 2; mt++) {
            const int r0 = bm + wm + mt * 16 + r_in;
#pragma unroll
            for (int nt = 0; nt < 8; nt++) {
                float o0 = fmaxf(acc[mt][nt][0] + bias2[nt][0], 0.f);
                float o1 = fmaxf(acc[mt][nt][1] + bias2[nt][1], 0.f);
                float o2 = fmaxf(acc[mt][nt][2] + bias2[nt][0], 0.f);
                float o3 = fmaxf(acc[mt][nt][3] + bias2[nt][1], 0.f);
                const int col = bn + wn + nt * 8 + c_in;
                uint32_t h, l;
                split2(o0, o1, h, l);
                *(uint32_t*)(Ch + (size_t)r0 * Ntot + col) = h;
                *(uint32_t*)(Cl + (size_t)r0 * Ntot + col) = l;
                split2(o2, o3, h, l);
                *(uint32_t*)(Ch + (size_t)(r0 + 8) * Ntot + col) = h;
                *(uint32_t*)(Cl + (size_t)(r0 + 8) * Ntot + col) = l;
            }
        }
    } else {
        float ss[2][2];
#pragma unroll
        for (int mt = 0; mt < 2; mt++) { ss[mt][0] = 0.f; ss[mt][1] = 0.f; }
#pragma unroll
        for (int mt = 0; mt < 2; mt++)
#pragma unroll
            for (int nt = 0; nt < 8; nt++) {
                acc[mt][nt][0] += bias2[nt][0];
                acc[mt][nt][1] += bias2[nt][1];
                acc[mt][nt][2] += bias2[nt][0];
                acc[mt][nt][3] += bias2[nt][1];
                ss[mt][0] = fmaf(acc[mt][nt][0], acc[mt][nt][0],
                            fmaf(acc[mt][nt][1], acc[mt][nt][1], ss[mt][0]));
                ss[mt][1] = fmaf(acc[mt][nt][2], acc[mt][nt][2],
                            fmaf(acc[mt][nt][3], acc[mt][nt][3], ss[mt][1]));
            }
#pragma unroll
        for (int m = 1; m <= 2; m <<= 1) {
#pragma unroll
            for (int mt = 0; mt < 2; mt++) {
                ss[mt][0] += __shfl_xor_sync(0xFFFFFFFFu, ss[mt][0], m);
                ss[mt][1] += __shfl_xor_sync(0xFFFFFFFFu, ss[mt][1], m);
            }
        }
        float* red = (float*)smem;
        float* invp = red + 256;
        const int half = wid >> 2;
        if ((lane & 3) == 0) {
#pragma unroll
            for (int mt = 0; mt < 2; mt++) {
                red[(wm + mt * 16 + r_in) * 2 + half]     = ss[mt][0];
                red[(wm + mt * 16 + r_in + 8) * 2 + half] = ss[mt][1];
            }
        }
        __syncthreads();
        if (tid < 128) {
            float s = red[tid * 2] + red[tid * 2 + 1];
            invp[tid] = 1.f / fmaxf(sqrtf(s), 1e-12f);
        }
        __syncthreads();
#pragma unroll
        for (int mt = 0; mt < 2; mt++) {
            const int rl = wm + mt * 16 + r_in;
            const float inv0 = invp[rl], inv1 = invp[rl + 8];
            const int r0 = bm + rl;
#pragma unroll
            for (int nt = 0; nt < 8; nt++) {
                const int col = wn + nt * 8 + c_in;
                uint32_t h, l;
                split2(acc[mt][nt][0] * inv0, acc[mt][nt][1] * inv0, h, l);
                *(uint32_t*)(Ch + (size_t)r0 * Ntot + col) = h;
                *(uint32_t*)(Cl + (size_t)r0 * Ntot + col) = l;
                split2(acc[mt][nt][2] * inv1, acc[mt][nt][3] * inv1, h, l);
                *(uint32_t*)(Ch + (size_t)(r0 + 8) * Ntot + col) = h;
                *(uint32_t*)(Cl + (size_t)(r0 + 8) * Ntot + col) = l;
            }
        }
    }
}

// ===========================================================================
// Final NT GEMM: C[8192,8192] = Zx @ Zy^T, K=128, bf16 hi/lo inputs.
// CTA tile 128(M) x 256(N); 8 warps 4x2; warp tile 32x128.
// ===========================================================================
#define NTSTR     272
#define N_A_HI    0
#define N_A_LO    (128 * NTSTR)
#define N_B_HI    (2 * 128 * NTSTR)
#define N_B_LO    (N_B_HI + 256 * NTSTR)
#define NT_SMEM   (N_B_LO + 256 * NTSTR)   // 208896 B

__global__ __launch_bounds__(256, 1) void gemm_nt_mma(
    const __nv_bfloat16* __restrict__ ZAh, const __nv_bfloat16* __restrict__ ZAl,
    const __nv_bfloat16* __restrict__ ZBh, const __nv_bfloat16* __restrict__ ZBl,
    float* __restrict__ C)
{
    extern __shared__ char smem[];
    const uint32_t sbase = smem_u32(smem);
    const int tid = threadIdx.x;
    const int bm = blockIdx.y << 7, bn = blockIdx.x << 8;

    // ---- cp.async tile fill ----
    {
        const int row  = tid >> 1;
        const int half = tid & 1;              // 64 bf16 = 128 B
        const uint32_t dof = (uint32_t)row * NTSTR + (uint32_t)half * 128;
        const char* sah = (const char*)(ZAh + (size_t)(bm + row) * LAT + half * 64);
        const char* sal = (const char*)(ZAl + (size_t)(bm + row) * LAT + half * 64);
#pragma unroll
        for (int c = 0; c < 8; c++) {
            cpa16(sbase + N_A_HI + dof + c * 16, sah + c * 16);
            cpa16(sbase + N_A_LO + dof + c * 16, sal + c * 16);
        }
#pragma unroll
        for (int rr = 0; rr < 2; rr++) {
            const int brow = rr * 128 + row;
            const uint32_t bof = (uint32_t)brow * NTSTR + (uint32_t)half * 128;
            const char* sbh = (const char*)(ZBh + (size_t)(bn + brow) * LAT + half * 64);
            const char* sbl = (const char*)(ZBl + (size_t)(bn + brow) * LAT + half * 64);
#pragma unroll
            for (int c = 0; c < 8; c++) {
                cpa16(sbase + N_B_HI + bof + c * 16, sbh + c * 16);
                cpa16(sbase + N_B_LO + bof + c * 16, sbl + c * 16);
            }
        }
    }
    CP_COMMIT();
    CP_WAIT0();
    __syncthreads();

    const int wid  = tid >> 5;
    const int lane = tid & 31;
    const int wm = (wid & 3) << 5;       // 0,32,64,96
    const int wn = (wid >> 2) << 7;      // 0,128
    const int lrow  = lane & 15;
    const int khalf = lane >> 4;

    float acc[2][16][4];
#pragma unroll
    for (int mt = 0; mt < 2; mt++)
#pragma unroll
        for (int nt = 0; nt < 16; nt++)
#pragma unroll
            for (int e = 0; e < 4; e++) acc[mt][nt][e] = 0.f;

#pragma unroll
    for (int ks = 0; ks < 8; ks++) {
        const uint32_t koff = (uint32_t)ks * 32 + (uint32_t)khalf * 16;

        uint32_t ah[2][4], al[2][4];
#pragma unroll
        for (int mt = 0; mt < 2; mt++) {
            const uint32_t ra = (uint32_t)(wm + mt * 16 + lrow) * NTSTR + koff;
            ldmx4(ah[mt], sbase + N_A_HI + ra);
            ldmx4(al[mt], sbase + N_A_LO + ra);
        }
#pragma unroll
        for (int np = 0; np < 8; np++) {
            const uint32_t rb = (uint32_t)(wn + np * 16 + lrow) * NTSTR + koff;
            uint32_t th[4], tl[4];
            ldmx4(th, sbase + N_B_HI + rb);
            ldmx4(tl, sbase + N_B_LO + rb);
#pragma unroll
            for (int mt = 0; mt < 2; mt++) {
                mma16816(acc[mt][2*np+0], ah[mt], th[0], th[2]);
                mma16816(acc[mt][2*np+1], ah[mt], th[1], th[3]);
            }
#pragma unroll
            for (int mt = 0; mt < 2; mt++) {
                mma16816(acc[mt][2*np+0], ah[mt], tl[0], tl[2]);
                mma16816(acc[mt][2*np+1], ah[mt], tl[1], tl[3]);
            }
#pragma unroll
            for (int mt = 0; mt < 2; mt++) {
                mma16816(acc[mt][2*np+0], al[mt], th[0], th[2]);
                mma16816(acc[mt][2*np+1], al[mt], th[1], th[3]);
            }
        }
    }

    // ---- epilogue: direct coalesced float2 stores ----
    const int r0 = bm + wm + (lane >> 2);
    const int c0 = bn + wn + ((lane & 3) << 1);
#pragma unroll
    for (int mt = 0; mt < 2; mt++) {
#pragma unroll
        for (int nt = 0; nt < 16; nt++) {
            float* p0 = C + (size_t)(r0 + mt * 16)     * NR + c0 + nt * 8;
            float* p1 = C + (size_t)(r0 + mt * 16 + 8) * NR + c0 + nt * 8;
            *(float2*)p0 = make_float2(acc[mt][nt][0], acc[mt][nt][1]);
            *(float2*)p1 = make_float2(acc[mt][nt][2], acc[mt][nt][3]);
        }
    }
}

// ===========================================================================
extern "C" void kernel_launch(void* const* d_in, const int* in_sizes, int n_in,
                              void* d_out, int out_size)
{
    const float* x  = (const float*)d_in[0];
    const float* y  = (const float*)d_in[1];
    const float* W1 = (const float*)d_in[2];
    const float* b1 = (const float*)d_in[3];
    const float* W2 = (const float*)d_in[4];
    const float* b2 = (const float*)d_in[5];
    const float* W3 = (const float*)d_in[6];
    const float* b3 = (const float*)d_in[7];
    float* out = (float*)d_out;

    __nv_bfloat16 *H1h, *H1l, *H2h, *H2l, *Zh, *Zl;
    cudaGetSymbolAddress((void**)&H1h, g_H1h);
    cudaGetSymbolAddress((void**)&H1l, g_H1l);
    cudaGetSymbolAddress((void**)&H2h, g_H2h);
    cudaGetSymbolAddress((void**)&H2l, g_H2l);
    cudaGetSymbolAddress((void**)&Zh,  g_Zh);
    cudaGetSymbolAddress((void**)&Zl,  g_Zl);
    __nv_bfloat16 *WT1h, *WT1l, *WT2h, *WT2l, *WT3h, *WT3l;
    cudaGetSymbolAddress((void**)&WT1h, g_WT1h);
    cudaGetSymbolAddress((void**)&WT1l, g_WT1l);
    cudaGetSymbolAddress((void**)&WT2h, g_WT2h);
    cudaGetSymbolAddress((void**)&WT2l, g_WT2l);
    cudaGetSymbolAddress((void**)&WT3h, g_WT3h);
    cudaGetSymbolAddress((void**)&WT3l, g_WT3l);

    cudaFuncSetAttribute(gemm_nt_mma, cudaFuncAttributeMaxDynamicSharedMemorySize, NT_SMEM);
    cudaFuncSetAttribute(gemm_enc<64,  false, false>, cudaFuncAttributeMaxDynamicSharedMemorySize, ENC_SMEM);
    cudaFuncSetAttribute(gemm_enc<512, true,  false>, cudaFuncAttributeMaxDynamicSharedMemorySize, ENC_SMEM);
    cudaFuncSetAttribute(gemm_enc<512, true,  true>,  cudaFuncAttributeMaxDynamicSharedMemorySize, ENC_SMEM);

    prep_wt<<<(DIM * HID + 255) / 256, 256>>>(W1, WT1h, WT1l, DIM, HID);
    prep_wt<<<(HID * HID + 255) / 256, 256>>>(W2, WT2h, WT2l, HID, HID);
    prep_wt<<<(HID * LAT + 255) / 256, 256>>>(W3, WT3h, WT3l, HID, LAT);

    // Layer 1 (fp32 A)
    dim3 g1(HID / 128, NR / 128);
    gemm_enc<64, false, false><<<g1, 256, ENC_SMEM>>>(
        x, nullptr, WT1h, WT1l, b1, H1h, H1l, HID);
    gemm_enc<64, false, false><<<g1, 256, ENC_SMEM>>>(
        y, nullptr, WT1h, WT1l, b1,
        H1h + (size_t)NR * HID, H1l + (size_t)NR * HID, HID);

    // Layer 2 (bf16 A)
    dim3 g2(HID / 128, 2 * NR / 128);
    gemm_enc<512, true, false><<<g2, 256, ENC_SMEM>>>(
        H1h, H1l, WT2h, WT2l, b2, H2h, H2l, HID);

    // Layer 3 + L2 normalize
    dim3 g3(1, 2 * NR / 128);
    gemm_enc<512, true, true><<<g3, 256, ENC_SMEM>>>(
        H2h, H2l, WT3h, WT3l, b3, Zh, Zl, LAT);

    // Similarity
    dim3 g4(NR / 256, NR / 128);
    gemm_nt_mma<<<g4, 256, NT_SMEM>>>(
        Zh, Zl, Zh + (size_t)NR * LAT, Zl + (size_t)NR * LAT, out);
}

// round 7
// speedup vs baseline: 2.2779x; 1.4248x over previous
#include <cuda_runtime.h>
#include <cuda_bf16.h>
#include <cuda_fp16.h>
#include <math.h>
#include <cstdint>

#define NR   8192
#define DIM  64
#define HID  512
#define LAT  128

// Scratch (device globals — allocation-free per harness rules)
__device__ __nv_bfloat16 g_H1h[2 * NR * HID], g_H1l[2 * NR * HID];
__device__ __nv_bfloat16 g_H2h[2 * NR * HID], g_H2l[2 * NR * HID];
__device__ __half        g_Zf [2 * NR * LAT];                       // fp16 Z
__device__ __nv_bfloat16 g_WT1h[HID * DIM], g_WT1l[HID * DIM];
__device__ __nv_bfloat16 g_WT2h[HID * HID], g_WT2l[HID * HID];
__device__ __nv_bfloat16 g_WT3h[LAT * HID], g_WT3l[LAT * HID];

// ===========================================================================
// helpers
// ===========================================================================
__device__ __forceinline__ uint32_t smem_u32(const void* p) {
    uint32_t a;
    asm("{ .reg .u64 t; cvta.to.shared.u64 t, %1; cvt.u32.u64 %0, t; }"
        : "=r"(a) : "l"(p));
    return a;
}
__device__ __forceinline__ void ldmx4(uint32_t* r, uint32_t addr) {
    asm volatile("ldmatrix.sync.aligned.m8n8.x4.shared.b16 {%0,%1,%2,%3}, [%4];"
                 : "=r"(r[0]), "=r"(r[1]), "=r"(r[2]), "=r"(r[3]) : "r"(addr));
}
__device__ __forceinline__ void mma16816(float* d, const uint32_t* a,
                                         uint32_t b0, uint32_t b1) {
    asm volatile(
        "mma.sync.aligned.m16n8k16.row.col.f32.bf16.bf16.f32 "
        "{%0,%1,%2,%3}, {%4,%5,%6,%7}, {%8,%9}, {%0,%1,%2,%3};"
        : "+f"(d[0]), "+f"(d[1]), "+f"(d[2]), "+f"(d[3])
        : "r"(a[0]), "r"(a[1]), "r"(a[2]), "r"(a[3]), "r"(b0), "r"(b1));
}
__device__ __forceinline__ void mma16816h(float* d, const uint32_t* a,
                                          uint32_t b0, uint32_t b1) {
    asm volatile(
        "mma.sync.aligned.m16n8k16.row.col.f32.f16.f16.f32 "
        "{%0,%1,%2,%3}, {%4,%5,%6,%7}, {%8,%9}, {%0,%1,%2,%3};"
        : "+f"(d[0]), "+f"(d[1]), "+f"(d[2]), "+f"(d[3])
        : "r"(a[0]), "r"(a[1]), "r"(a[2]), "r"(a[3]), "r"(b0), "r"(b1));
}
__device__ __forceinline__ void cpa16(uint32_t dst, const void* src) {
    asm volatile("cp.async.cg.shared.global [%0], [%1], 16;"
                 :: "r"(dst), "l"(src));
}
#define CP_COMMIT() asm volatile("cp.async.commit_group;")
#define CP_WAIT0()  asm volatile("cp.async.wait_group 0;" ::: "memory")

__device__ __forceinline__ void split8(const float* f, uint4& hv, uint4& lv) {
    uint32_t hw[4], lw[4];
#pragma unroll
    for (int j = 0; j < 4; j++) {
        float a = f[2*j], b = f[2*j+1];
        float ha = __bfloat162float(__float2bfloat16(a));
        float hb = __bfloat162float(__float2bfloat16(b));
        asm("cvt.rn.bf16x2.f32 %0, %1, %2;" : "=r"(hw[j]) : "f"(b), "f"(a));
        float la = a - ha, lb = b - hb;
        asm("cvt.rn.bf16x2.f32 %0, %1, %2;" : "=r"(lw[j]) : "f"(lb), "f"(la));
    }
    hv = make_uint4(hw[0], hw[1], hw[2], hw[3]);
    lv = make_uint4(lw[0], lw[1], lw[2], lw[3]);
}
__device__ __forceinline__ void split2(float a, float b, uint32_t& h, uint32_t& l) {
    float ha = __bfloat162float(__float2bfloat16(a));
    float hb = __bfloat162float(__float2bfloat16(b));
    asm("cvt.rn.bf16x2.f32 %0, %1, %2;" : "=r"(h) : "f"(b), "f"(a));
    float la = a - ha, lb = b - hb;
    asm("cvt.rn.bf16x2.f32 %0, %1, %2;" : "=r"(l) : "f"(lb), "f"(la));
}
__device__ __forceinline__ uint32_t packh2(float a, float b) {
    uint32_t r;
    asm("cvt.rn.f16x2.f32 %0, %1, %2;" : "=r"(r) : "f"(b), "f"(a));
    return r;
}

// ===========================================================================
// prep: WT[n*K+k] = hi/lo bf16 split of W[k*N+n]
// ===========================================================================
__global__ void prep_wt(const float* __restrict__ W,
                        __nv_bfloat16* __restrict__ WTh,
                        __nv_bfloat16* __restrict__ WTl, int K, int N) {
    int idx = blockIdx.x * blockDim.x + threadIdx.x;
    if (idx >= K * N) return;
    int n = idx / K, k = idx - n * K;
    float v = W[(size_t)k * N + n];
    __nv_bfloat16 h = __float2bfloat16(v);
    WTh[idx] = h;
    WTl[idx] = __float2bfloat16(v - __bfloat162float(h));
}

// ===========================================================================
// Encoder mma GEMM. CTA 128x128, BK=64, 8 warps (4x2), 3-pass bf16 hi/lo.
// NORM=false: bias+ReLU -> bf16 hi/lo out.  NORM=true: bias + row L2 norm
// (Ntot==128) -> fp16 out (Ch reinterpreted as __half*, Cl unused).
// ===========================================================================
#define STR2      144
#define T2_BYTES  (128 * STR2)
#define E_A_HI    0
#define E_A_LO    (T2_BYTES)
#define E_B_HI    (2 * T2_BYTES)
#define E_B_LO    (3 * T2_BYTES)
#define ENC_SMEM  (4 * T2_BYTES)

template<int K, bool A_BF16, bool NORM>
__global__ __launch_bounds__(256, 1) void gemm_enc(
    const void* __restrict__ A0, const void* __restrict__ A1,
    const __nv_bfloat16* __restrict__ Bh, const __nv_bfloat16* __restrict__ Bl,
    const float* __restrict__ bias,
    __nv_bfloat16* __restrict__ Ch, __nv_bfloat16* __restrict__ Cl, int Ntot)
{
    extern __shared__ char smem[];
    const uint32_t sbase = smem_u32(smem);
    const int tid = threadIdx.x;
    const int bm = blockIdx.y << 7, bn = blockIdx.x << 7;
    const int wid = tid >> 5, lane = tid & 31;
    const int wm = (wid & 3) << 5, wn = (wid >> 2) << 6;
    const int lrow = lane & 15, khalf = lane >> 4;

    float acc[2][8][4];
#pragma unroll
    for (int mt = 0; mt < 2; mt++)
#pragma unroll
        for (int nt = 0; nt < 8; nt++)
#pragma unroll
            for (int e = 0; e < 4; e++) acc[mt][nt][e] = 0.f;

    const int lr  = tid >> 1;
    const int ksg = (tid & 1) << 5;

    for (int k0 = 0; k0 < K; k0 += 64) {
        const uint32_t ob = (uint32_t)lr * STR2 + (uint32_t)ksg * 2;
        if (A_BF16) {
            const __nv_bfloat16* ah = (const __nv_bfloat16*)A0 + (size_t)(bm + lr) * K + k0 + ksg;
            const __nv_bfloat16* al = (const __nv_bfloat16*)A1 + (size_t)(bm + lr) * K + k0 + ksg;
#pragma unroll
            for (int c = 0; c < 4; c++) {
                cpa16(sbase + E_A_HI + ob + c * 16, (const char*)ah + c * 16);
                cpa16(sbase + E_A_LO + ob + c * 16, (const char*)al + c * 16);
            }
        } else {
            const float* ap = (const float*)A0 + (size_t)(bm + lr) * K + k0 + ksg;
#pragma unroll
            for (int c = 0; c < 4; c++) {
                float4 f0 = *(const float4*)(ap + c * 8);
                float4 f1 = *(const float4*)(ap + c * 8 + 4);
                float f[8] = {f0.x,f0.y,f0.z,f0.w,f1.x,f1.y,f1.z,f1.w};
                uint4 hv, lv;
                split8(f, hv, lv);
                *(uint4*)(smem + E_A_HI + ob + c * 16) = hv;
                *(uint4*)(smem + E_A_LO + ob + c * 16) = lv;
            }
        }
        {
            const char* bph = (const char*)(Bh + (size_t)(bn + lr) * K + k0 + ksg);
            const char* bpl = (const char*)(Bl + (size_t)(bn + lr) * K + k0 + ksg);
#pragma unroll
            for (int c = 0; c < 4; c++) {
                cpa16(sbase + E_B_HI + ob + c * 16, bph + c * 16);
                cpa16(sbase + E_B_LO + ob + c * 16, bpl + c * 16);
            }
        }
        CP_COMMIT();
        CP_WAIT0();
        __syncthreads();

#pragma unroll
        for (int ks = 0; ks < 4; ks++) {
            const uint32_t koff = (uint32_t)ks * 32 + (uint32_t)khalf * 16;
            uint32_t ah[2][4], al[2][4];
#pragma unroll
            for (int mt = 0; mt < 2; mt++) {
                const uint32_t ra = (uint32_t)(wm + mt * 16 + lrow) * STR2 + koff;
                ldmx4(ah[mt], sbase + E_A_HI + ra);
                ldmx4(al[mt], sbase + E_A_LO + ra);
            }
#pragma unroll
            for (int np = 0; np < 4; np++) {
                const uint32_t rb = (uint32_t)(wn + np * 16 + lrow) * STR2 + koff;
                uint32_t th[4], tl[4];
                ldmx4(th, sbase + E_B_HI + rb);
                ldmx4(tl, sbase + E_B_LO + rb);
#pragma unroll
                for (int mt = 0; mt < 2; mt++) {
                    mma16816(acc[mt][2*np+0], ah[mt], th[0], th[2]);
                    mma16816(acc[mt][2*np+1], ah[mt], th[1], th[3]);
                }
#pragma unroll
                for (int mt = 0; mt < 2; mt++) {
                    mma16816(acc[mt][2*np+0], ah[mt], tl[0], tl[2]);
                    mma16816(acc[mt][2*np+1], ah[mt], tl[1], tl[3]);
                }
#pragma unroll
                for (int mt = 0; mt < 2; mt++) {
                    mma16816(acc[mt][2*np+0], al[mt], th[0], th[2]);
                    mma16816(acc[mt][2*np+1], al[mt], th[1], th[3]);
                }
            }
        }
        __syncthreads();
    }

    const int r_in = lane >> 2;
    const int c_in = (lane & 3) << 1;

    float bias2[8][2];
#pragma unroll
    for (int nt = 0; nt < 8; nt++) {
        bias2[nt][0] = bias[bn + wn + nt * 8 + c_in];
        bias2[nt][1] = bias[bn + wn + nt * 8 + c_in + 1];
    }

    if (!NORM) {
#pragma unroll
        for (int mt = 0; mt < 2; mt++) {
            const int r0 = bm + wm + mt * 16 + r_in;
#pragma unroll
            for (int nt = 0; nt < 8; nt++) {
                float o0 = fmaxf(acc[mt][nt][0] + bias2[nt][0], 0.f);
                float o1 = fmaxf(acc[mt][nt][1] + bias2[nt][1], 0.f);
                float o2 = fmaxf(acc[mt][nt][2] + bias2[nt][0], 0.f);
                float o3 = fmaxf(acc[mt][nt][3] + bias2[nt][1], 0.f);
                const int col = bn + wn + nt * 8 + c_in;
                uint32_t h, l;
                split2(o0, o1, h, l);
                *(uint32_t*)(Ch + (size_t)r0 * Ntot + col) = h;
                *(uint32_t*)(Cl + (size_t)r0 * Ntot + col) = l;
                split2(o2, o3, h, l);
                *(uint32_t*)(Ch + (size_t)(r0 + 8) * Ntot + col) = h;
                *(uint32_t*)(Cl + (size_t)(r0 + 8) * Ntot + col) = l;
            }
        }
    } else {
        float ss[2][2];
#pragma unroll
        for (int mt = 0; mt < 2; mt++) { ss[mt][0] = 0.f; ss[mt][1] = 0.f; }
#pragma unroll
        for (int mt = 0; mt < 2; mt++)
#pragma unroll
            for (int nt = 0; nt < 8; nt++) {
                acc[mt][nt][0] += bias2[nt][0];
                acc[mt][nt][1] += bias2[nt][1];
                acc[mt][nt][2] += bias2[nt][0];
                acc[mt][nt][3] += bias2[nt][1];
                ss[mt][0] = fmaf(acc[mt][nt][0], acc[mt][nt][0],
                            fmaf(acc[mt][nt][1], acc[mt][nt][1], ss[mt][0]));
                ss[mt][1] = fmaf(acc[mt][nt][2], acc[mt][nt][2],
                            fmaf(acc[mt][nt][3], acc[mt][nt][3], ss[mt][1]));
            }
#pragma unroll
        for (int m = 1; m <= 2; m <<= 1) {
#pragma unroll
            for (int mt = 0; mt < 2; mt++) {
                ss[mt][0] += __shfl_xor_sync(0xFFFFFFFFu, ss[mt][0], m);
                ss[mt][1] += __shfl_xor_sync(0xFFFFFFFFu, ss[mt][1], m);
            }
        }
        float* red = (float*)smem;
        float* invp = red + 256;
        const int half = wid >> 2;
        if ((lane & 3) == 0) {
#pragma unroll
            for (int mt = 0; mt < 2; mt++) {
                red[(wm + mt * 16 + r_in) * 2 + half]     = ss[mt][0];
                red[(wm + mt * 16 + r_in + 8) * 2 + half] = ss[mt][1];
            }
        }
        __syncthreads();
        if (tid < 128) {
            float s = red[tid * 2] + red[tid * 2 + 1];
            invp[tid] = 1.f / fmaxf(sqrtf(s), 1e-12f);
        }
        __syncthreads();
        __half* Zf = (__half*)Ch;
#pragma unroll
        for (int mt = 0; mt < 2; mt++) {
            const int rl = wm + mt * 16 + r_in;
            const float inv0 = invp[rl], inv1 = invp[rl + 8];
            const int r0 = bm + rl;
#pragma unroll
            for (int nt = 0; nt < 8; nt++) {
                const int col = wn + nt * 8 + c_in;
                *(uint32_t*)(Zf + (size_t)r0 * Ntot + col) =
                    packh2(acc[mt][nt][0] * inv0, acc[mt][nt][1] * inv0);
                *(uint32_t*)(Zf + (size_t)(r0 + 8) * Ntot + col) =
                    packh2(acc[mt][nt][2] * inv1, acc[mt][nt][3] * inv1);
            }
        }
    }
}

// ===========================================================================
// Final NT GEMM: C[8192,8192] = Zx @ Zy^T, K=128, single-pass fp16.
// CTA tile 128x128; 8 warps 4x2; 2 CTAs/SM.
// ===========================================================================
#define FSTR      272
#define F_A       0
#define F_B       (128 * FSTR)
#define NTF_SMEM  (2 * 128 * FSTR)       // 69632 B

__global__ __launch_bounds__(256, 2) void gemm_nt_f16(
    const __half* __restrict__ ZA, const __half* __restrict__ ZB,
    float* __restrict__ C)
{
    extern __shared__ char smem[];
    const uint32_t sbase = smem_u32(smem);
    const int tid = threadIdx.x;
    const int bm = blockIdx.y << 7, bn = blockIdx.x << 7;

    // ---- cp.async tile fill (A: 128x128 fp16, B: 128x128 fp16) ----
    {
        const int row  = tid >> 1;
        const int half = tid & 1;            // 64 halves = 128 B
        const uint32_t dof = (uint32_t)row * FSTR + (uint32_t)half * 128;
        const char* sa = (const char*)(ZA + (size_t)(bm + row) * LAT + half * 64);
        const char* sb = (const char*)(ZB + (size_t)(bn + row) * LAT + half * 64);
#pragma unroll
        for (int c = 0; c < 8; c++) {
            cpa16(sbase + F_A + dof + c * 16, sa + c * 16);
            cpa16(sbase + F_B + dof + c * 16, sb + c * 16);
        }
    }
    CP_COMMIT();
    CP_WAIT0();
    __syncthreads();

    const int wid  = tid >> 5;
    const int lane = tid & 31;
    const int wm = (wid & 3) << 5;
    const int wn = (wid >> 2) << 6;
    const int lrow  = lane & 15;
    const int khalf = lane >> 4;

    float acc[2][8][4];
#pragma unroll
    for (int mt = 0; mt < 2; mt++)
#pragma unroll
        for (int nt = 0; nt < 8; nt++)
#pragma unroll
            for (int e = 0; e < 4; e++) acc[mt][nt][e] = 0.f;

#pragma unroll
    for (int ks = 0; ks < 8; ks++) {
        const uint32_t koff = (uint32_t)ks * 32 + (uint32_t)khalf * 16;
        uint32_t a[2][4];
#pragma unroll
        for (int mt = 0; mt < 2; mt++) {
            const uint32_t ra = (uint32_t)(wm + mt * 16 + lrow) * FSTR + koff;
            ldmx4(a[mt], sbase + F_A + ra);
        }
#pragma unroll
        for (int np = 0; np < 4; np++) {
            const uint32_t rb = (uint32_t)(wn + np * 16 + lrow) * FSTR + koff;
            uint32_t t[4];
            ldmx4(t, sbase + F_B + rb);
#pragma unroll
            for (int mt = 0; mt < 2; mt++) {
                mma16816h(acc[mt][2*np+0], a[mt], t[0], t[2]);
                mma16816h(acc[mt][2*np+1], a[mt], t[1], t[3]);
            }
        }
    }

    // ---- epilogue ----
    const int r0 = bm + wm + (lane >> 2);
    const int c0 = bn + wn + ((lane & 3) << 1);
#pragma unroll
    for (int mt = 0; mt < 2; mt++) {
#pragma unroll
        for (int nt = 0; nt < 8; nt++) {
            float* p0 = C + (size_t)(r0 + mt * 16)     * NR + c0 + nt * 8;
            float* p1 = C + (size_t)(r0 + mt * 16 + 8) * NR + c0 + nt * 8;
            *(float2*)p0 = make_float2(acc[mt][nt][0], acc[mt][nt][1]);
            *(float2*)p1 = make_float2(acc[mt][nt][2], acc[mt][nt][3]);
        }
    }
}

// ===========================================================================
extern "C" void kernel_launch(void* const* d_in, const int* in_sizes, int n_in,
                              void* d_out, int out_size)
{
    const float* x  = (const float*)d_in[0];
    const float* y  = (const float*)d_in[1];
    const float* W1 = (const float*)d_in[2];
    const float* b1 = (const float*)d_in[3];
    const float* W2 = (const float*)d_in[4];
    const float* b2 = (const float*)d_in[5];
    const float* W3 = (const float*)d_in[6];
    const float* b3 = (const float*)d_in[7];
    float* out = (float*)d_out;

    __nv_bfloat16 *H1h, *H1l, *H2h, *H2l;
    __half *Zf;
    cudaGetSymbolAddress((void**)&H1h, g_H1h);
    cudaGetSymbolAddress((void**)&H1l, g_H1l);
    cudaGetSymbolAddress((void**)&H2h, g_H2h);
    cudaGetSymbolAddress((void**)&H2l, g_H2l);
    cudaGetSymbolAddress((void**)&Zf,  g_Zf);
    __nv_bfloat16 *WT1h, *WT1l, *WT2h, *WT2l, *WT3h, *WT3l;
    cudaGetSymbolAddress((void**)&WT1h, g_WT1h);
    cudaGetSymbolAddress((void**)&WT1l, g_WT1l);
    cudaGetSymbolAddress((void**)&WT2h, g_WT2h);
    cudaGetSymbolAddress((void**)&WT2l, g_WT2l);
    cudaGetSymbolAddress((void**)&WT3h, g_WT3h);
    cudaGetSymbolAddress((void**)&WT3l, g_WT3l);

    cudaFuncSetAttribute(gemm_nt_f16, cudaFuncAttributeMaxDynamicSharedMemorySize, NTF_SMEM);
    cudaFuncSetAttribute(gemm_enc<64,  false, false>, cudaFuncAttributeMaxDynamicSharedMemorySize, ENC_SMEM);
    cudaFuncSetAttribute(gemm_enc<512, true,  false>, cudaFuncAttributeMaxDynamicSharedMemorySize, ENC_SMEM);
    cudaFuncSetAttribute(gemm_enc<512, true,  true>,  cudaFuncAttributeMaxDynamicSharedMemorySize, ENC_SMEM);

    prep_wt<<<(DIM * HID + 255) / 256, 256>>>(W1, WT1h, WT1l, DIM, HID);
    prep_wt<<<(HID * HID + 255) / 256, 256>>>(W2, WT2h, WT2l, HID, HID);
    prep_wt<<<(HID * LAT + 255) / 256, 256>>>(W3, WT3h, WT3l, HID, LAT);

    // Layer 1 (fp32 A)
    dim3 g1(HID / 128, NR / 128);
    gemm_enc<64, false, false><<<g1, 256, ENC_SMEM>>>(
        x, nullptr, WT1h, WT1l, b1, H1h, H1l, HID);
    gemm_enc<64, false, false><<<g1, 256, ENC_SMEM>>>(
        y, nullptr, WT1h, WT1l, b1,
        H1h + (size_t)NR * HID, H1l + (size_t)NR * HID, HID);

    // Layer 2 (bf16 A)
    dim3 g2(HID / 128, 2 * NR / 128);
    gemm_enc<512, true, false><<<g2, 256, ENC_SMEM>>>(
        H1h, H1l, WT2h, WT2l, b2, H2h, H2l, HID);

    // Layer 3 + L2 normalize -> fp16 Z
    dim3 g3(1, 2 * NR / 128);
    gemm_enc<512, true, true><<<g3, 256, ENC_SMEM>>>(
        H2h, H2l, WT3h, WT3l, b3, (__nv_bfloat16*)Zf, nullptr, LAT);

    // Similarity (single-pass fp16)
    dim3 g4(NR / 128, NR / 128);
    gemm_nt_f16<<<g4, 256, NTF_SMEM>>>(Zf, Zf + (size_t)NR * LAT, out);
}

// round 8
// speedup vs baseline: 3.3891x; 1.4878x over previous
#include <cuda_runtime.h>
#include <cuda_bf16.h>
#include <cuda_fp16.h>
#include <math.h>
#include <cstdint>

#define NR   8192
#define DIM  64
#define HID  512
#define LAT  128

// Scratch (device globals — allocation-free per harness rules)
__device__ __half g_H1[2 * NR * HID];    // 16 MB
__device__ __half g_H2[2 * NR * HID];    // 16 MB
__device__ __half g_Zf[2 * NR * LAT];    //  4 MB
__device__ __half g_WT1[HID * DIM];
__device__ __half g_WT2[HID * HID];
__device__ __half g_WT3[LAT * HID];

// ===========================================================================
// helpers
// ===========================================================================
__device__ __forceinline__ uint32_t smem_u32(const void* p) {
    uint32_t a;
    asm("{ .reg .u64 t; cvta.to.shared.u64 t, %1; cvt.u32.u64 %0, t; }"
        : "=r"(a) : "l"(p));
    return a;
}
__device__ __forceinline__ void ldmx4(uint32_t* r, uint32_t addr) {
    asm volatile("ldmatrix.sync.aligned.m8n8.x4.shared.b16 {%0,%1,%2,%3}, [%4];"
                 : "=r"(r[0]), "=r"(r[1]), "=r"(r[2]), "=r"(r[3]) : "r"(addr));
}
__device__ __forceinline__ void mma16816h(float* d, const uint32_t* a,
                                          uint32_t b0, uint32_t b1) {
    asm volatile(
        "mma.sync.aligned.m16n8k16.row.col.f32.f16.f16.f32 "
        "{%0,%1,%2,%3}, {%4,%5,%6,%7}, {%8,%9}, {%0,%1,%2,%3};"
        : "+f"(d[0]), "+f"(d[1]), "+f"(d[2]), "+f"(d[3])
        : "r"(a[0]), "r"(a[1]), "r"(a[2]), "r"(a[3]), "r"(b0), "r"(b1));
}
__device__ __forceinline__ void cpa16(uint32_t dst, const void* src) {
    asm volatile("cp.async.cg.shared.global [%0], [%1], 16;"
                 :: "r"(dst), "l"(src));
}
#define CP_COMMIT() asm volatile("cp.async.commit_group;")
#define CP_WAIT0()  asm volatile("cp.async.wait_group 0;" ::: "memory")
#define CP_WAIT1()  asm volatile("cp.async.wait_group 1;" ::: "memory")

__device__ __forceinline__ uint32_t packh2(float a, float b) {
    uint32_t r;
    asm("cvt.rn.f16x2.f32 %0, %1, %2;" : "=r"(r) : "f"(b), "f"(a));
    return r;
}

// ===========================================================================
// prep: WT[n*K+k] = fp16(W[k*N+n])
// ===========================================================================
__global__ void prep_wt(const float* __restrict__ W,
                        __half* __restrict__ WT, int K, int N) {
    int idx = blockIdx.x * blockDim.x + threadIdx.x;
    if (idx >= K * N) return;
    int n = idx / K, k = idx - n * K;
    WT[idx] = __float2half(W[(size_t)k * N + n]);
}

// ===========================================================================
// Encoder mma GEMM, single-pass fp16, double-buffered.
// CTA 128x128, BK=64, 8 warps (4x2), 2 CTAs/SM.
// A_FP32: A is fp32 (split x/y at row NR); else fp16.
// NORM=false: bias+ReLU -> fp16. NORM=true: bias + row L2 norm -> fp16 Z.
// ===========================================================================
#define ESTR      144
#define ET        (128 * ESTR)           // 18432
#define ENC_SMEM  (4 * ET)               // 73728: 2 bufs x (A + B)

template<int K, bool A_FP32, bool NORM>
__global__ __launch_bounds__(256, 2) void gemm_enc(
    const void* __restrict__ Ax, const void* __restrict__ Ay,
    const __half* __restrict__ B,
    const float* __restrict__ bias,
    __half* __restrict__ Cf, int Ntot)
{
    constexpr int CH = K / 64;
    extern __shared__ char smem[];
    const uint32_t sbase = smem_u32(smem);
    const int tid = threadIdx.x;
    const int bmg = blockIdx.y << 7, bn = blockIdx.x << 7;
    const int wid = tid >> 5, lane = tid & 31;
    const int wm = (wid & 3) << 5, wn = (wid >> 2) << 6;
    const int lrow = lane & 15, khalf = lane >> 4;

    // resolve x/y half for fp32 input (block never straddles NR)
    const float* Af32 = nullptr;
    const __half* Af16 = nullptr;
    int bm;
    if (A_FP32) {
        Af32 = (bmg < NR) ? (const float*)Ax : (const float*)Ay;
        bm = (bmg < NR) ? bmg : bmg - NR;
    } else {
        Af16 = (const __half*)Ax;
        bm = bmg;
    }

    float acc[2][8][4];
#pragma unroll
    for (int mt = 0; mt < 2; mt++)
#pragma unroll
        for (int nt = 0; nt < 8; nt++)
#pragma unroll
            for (int e = 0; e < 4; e++) acc[mt][nt][e] = 0.f;

    const int lr  = tid >> 1;
    const int ksg = (tid & 1) << 5;      // 0 or 32 k-elements

    // chunk loader
    auto load_chunk = [&](int c, int buf) {
        const uint32_t abase = sbase + (uint32_t)(buf * 2) * ET;
        const uint32_t bbase = abase + ET;
        const uint32_t ob = (uint32_t)lr * ESTR + (uint32_t)ksg * 2;
        if (A_FP32) {
            const float* ap = Af32 + (size_t)(bm + lr) * K + c * 64 + ksg;
#pragma unroll
            for (int q = 0; q < 4; q++) {
                float4 f0 = *(const float4*)(ap + q * 8);
                float4 f1 = *(const float4*)(ap + q * 8 + 4);
                uint4 v;
                v.x = packh2(f0.x, f0.y); v.y = packh2(f0.z, f0.w);
                v.z = packh2(f1.x, f1.y); v.w = packh2(f1.z, f1.w);
                *(uint4*)(smem + (abase - sbase) + ob + q * 16) = v;
            }
        } else {
            const char* ap = (const char*)(Af16 + (size_t)(bm + lr) * K + c * 64 + ksg);
#pragma unroll
            for (int q = 0; q < 4; q++)
                cpa16(abase + ob + q * 16, ap + q * 16);
        }
        const char* bp = (const char*)(B + (size_t)(bn + lr) * K + c * 64 + ksg);
#pragma unroll
        for (int q = 0; q < 4; q++)
            cpa16(bbase + ob + q * 16, bp + q * 16);
    };

    load_chunk(0, 0);
    CP_COMMIT();

    for (int c = 0; c < CH; c++) {
        if (c + 1 < CH) {
            load_chunk(c + 1, (c + 1) & 1);
            CP_COMMIT();
            CP_WAIT1();
        } else {
            CP_WAIT0();
        }
        __syncthreads();

        const uint32_t abase = sbase + (uint32_t)((c & 1) * 2) * ET;
        const uint32_t bbase = abase + ET;
#pragma unroll
        for (int ks = 0; ks < 4; ks++) {
            const uint32_t koff = (uint32_t)ks * 32 + (uint32_t)khalf * 16;
            uint32_t a[2][4];
#pragma unroll
            for (int mt = 0; mt < 2; mt++) {
                const uint32_t ra = (uint32_t)(wm + mt * 16 + lrow) * ESTR + koff;
                ldmx4(a[mt], abase + ra);
            }
#pragma unroll
            for (int np = 0; np < 4; np++) {
                const uint32_t rb = (uint32_t)(wn + np * 16 + lrow) * ESTR + koff;
                uint32_t t[4];
                ldmx4(t, bbase + rb);
#pragma unroll
                for (int mt = 0; mt < 2; mt++) {
                    mma16816h(acc[mt][2*np+0], a[mt], t[0], t[2]);
                    mma16816h(acc[mt][2*np+1], a[mt], t[1], t[3]);
                }
            }
        }
        __syncthreads();
    }

    const int r_in = lane >> 2;
    const int c_in = (lane & 3) << 1;

    float bias2[8][2];
#pragma unroll
    for (int nt = 0; nt < 8; nt++) {
        bias2[nt][0] = bias[bn + wn + nt * 8 + c_in];
        bias2[nt][1] = bias[bn + wn + nt * 8 + c_in + 1];
    }

    if (!NORM) {
#pragma unroll
        for (int mt = 0; mt < 2; mt++) {
            const int r0 = bmg + wm + mt * 16 + r_in;
#pragma unroll
            for (int nt = 0; nt < 8; nt++) {
                float o0 = fmaxf(acc[mt][nt][0] + bias2[nt][0], 0.f);
                float o1 = fmaxf(acc[mt][nt][1] + bias2[nt][1], 0.f);
                float o2 = fmaxf(acc[mt][nt][2] + bias2[nt][0], 0.f);
                float o3 = fmaxf(acc[mt][nt][3] + bias2[nt][1], 0.f);
                const int col = bn + wn + nt * 8 + c_in;
                *(uint32_t*)(Cf + (size_t)r0 * Ntot + col)       = packh2(o0, o1);
                *(uint32_t*)(Cf + (size_t)(r0 + 8) * Ntot + col) = packh2(o2, o3);
            }
        }
    } else {
        float ss[2][2];
#pragma unroll
        for (int mt = 0; mt < 2; mt++) { ss[mt][0] = 0.f; ss[mt][1] = 0.f; }
#pragma unroll
        for (int mt = 0; mt < 2; mt++)
#pragma unroll
            for (int nt = 0; nt < 8; nt++) {
                acc[mt][nt][0] += bias2[nt][0];
                acc[mt][nt][1] += bias2[nt][1];
                acc[mt][nt][2] += bias2[nt][0];
                acc[mt][nt][3] += bias2[nt][1];
                ss[mt][0] = fmaf(acc[mt][nt][0], acc[mt][nt][0],
                            fmaf(acc[mt][nt][1], acc[mt][nt][1], ss[mt][0]));
                ss[mt][1] = fmaf(acc[mt][nt][2], acc[mt][nt][2],
                            fmaf(acc[mt][nt][3], acc[mt][nt][3], ss[mt][1]));
            }
#pragma unroll
        for (int m = 1; m <= 2; m <<= 1) {
#pragma unroll
            for (int mt = 0; mt < 2; mt++) {
                ss[mt][0] += __shfl_xor_sync(0xFFFFFFFFu, ss[mt][0], m);
                ss[mt][1] += __shfl_xor_sync(0xFFFFFFFFu, ss[mt][1], m);
            }
        }
        float* red = (float*)smem;          // [128][2]
        float* invp = red + 256;            // [128]
        const int half = wid >> 2;
        if ((lane & 3) == 0) {
#pragma unroll
            for (int mt = 0; mt < 2; mt++) {
                red[(wm + mt * 16 + r_in) * 2 + half]     = ss[mt][0];
                red[(wm + mt * 16 + r_in + 8) * 2 + half] = ss[mt][1];
            }
        }
        __syncthreads();
        if (tid < 128) {
            float s = red[tid * 2] + red[tid * 2 + 1];
            invp[tid] = 1.f / fmaxf(sqrtf(s), 1e-12f);
        }
        __syncthreads();
#pragma unroll
        for (int mt = 0; mt < 2; mt++) {
            const int rl = wm + mt * 16 + r_in;
            const float inv0 = invp[rl], inv1 = invp[rl + 8];
            const int r0 = bmg + rl;
#pragma unroll
            for (int nt = 0; nt < 8; nt++) {
                const int col = wn + nt * 8 + c_in;
                *(uint32_t*)(Cf + (size_t)r0 * Ntot + col) =
                    packh2(acc[mt][nt][0] * inv0, acc[mt][nt][1] * inv0);
                *(uint32_t*)(Cf + (size_t)(r0 + 8) * Ntot + col) =
                    packh2(acc[mt][nt][2] * inv1, acc[mt][nt][3] * inv1);
            }
        }
    }
}

// ===========================================================================
// Final NT GEMM: C[8192,8192] = Zx @ Zy^T, K=128, single-pass fp16.
// CTA 128x128; 8 warps 4x2; 2 CTAs/SM. (validated round 7)
// ===========================================================================
#define FSTR      272
#define F_A       0
#define F_B       (128 * FSTR)
#define NTF_SMEM  (2 * 128 * FSTR)       // 69632 B

__global__ __launch_bounds__(256, 2) void gemm_nt_f16(
    const __half* __restrict__ ZA, const __half* __restrict__ ZB,
    float* __restrict__ C)
{
    extern __shared__ char smem[];
    const uint32_t sbase = smem_u32(smem);
    const int tid = threadIdx.x;
    const int bm = blockIdx.y << 7, bn = blockIdx.x << 7;

    {
        const int row  = tid >> 1;
        const int half = tid & 1;
        const uint32_t dof = (uint32_t)row * FSTR + (uint32_t)half * 128;
        const char* sa = (const char*)(ZA + (size_t)(bm + row) * LAT + half * 64);
        const char* sb = (const char*)(ZB + (size_t)(bn + row) * LAT + half * 64);
#pragma unroll
        for (int c = 0; c < 8; c++) {
            cpa16(sbase + F_A + dof + c * 16, sa + c * 16);
            cpa16(sbase + F_B + dof + c * 16, sb + c * 16);
        }
    }
    CP_COMMIT();
    CP_WAIT0();
    __syncthreads();

    const int wid  = tid >> 5;
    const int lane = tid & 31;
    const int wm = (wid & 3) << 5;
    const int wn = (wid >> 2) << 6;
    const int lrow  = lane & 15;
    const int khalf = lane >> 4;

    float acc[2][8][4];
#pragma unroll
    for (int mt = 0; mt < 2; mt++)
#pragma unroll
        for (int nt = 0; nt < 8; nt++)
#pragma unroll
            for (int e = 0; e < 4; e++) acc[mt][nt][e] = 0.f;

#pragma unroll
    for (int ks = 0; ks < 8; ks++) {
        const uint32_t koff = (uint32_t)ks * 32 + (uint32_t)khalf * 16;
        uint32_t a[2][4];
#pragma unroll
        for (int mt = 0; mt < 2; mt++) {
            const uint32_t ra = (uint32_t)(wm + mt * 16 + lrow) * FSTR + koff;
            ldmx4(a[mt], sbase + F_A + ra);
        }
#pragma unroll
        for (int np = 0; np < 4; np++) {
            const uint32_t rb = (uint32_t)(wn + np * 16 + lrow) * FSTR + koff;
            uint32_t t[4];
            ldmx4(t, sbase + F_B + rb);
#pragma unroll
            for (int mt = 0; mt < 2; mt++) {
                mma16816h(acc[mt][2*np+0], a[mt], t[0], t[2]);
                mma16816h(acc[mt][2*np+1], a[mt], t[1], t[3]);
            }
        }
    }

    const int r0 = bm + wm + (lane >> 2);
    const int c0 = bn + wn + ((lane & 3) << 1);
#pragma unroll
    for (int mt = 0; mt < 2; mt++) {
#pragma unroll
        for (int nt = 0; nt < 8; nt++) {
            float* p0 = C + (size_t)(r0 + mt * 16)     * NR + c0 + nt * 8;
            float* p1 = C + (size_t)(r0 + mt * 16 + 8) * NR + c0 + nt * 8;
            *(float2*)p0 = make_float2(acc[mt][nt][0], acc[mt][nt][1]);
            *(float2*)p1 = make_float2(acc[mt][nt][2], acc[mt][nt][3]);
        }
    }
}

// ===========================================================================
extern "C" void kernel_launch(void* const* d_in, const int* in_sizes, int n_in,
                              void* d_out, int out_size)
{
    const float* x  = (const float*)d_in[0];
    const float* y  = (const float*)d_in[1];
    const float* W1 = (const float*)d_in[2];
    const float* b1 = (const float*)d_in[3];
    const float* W2 = (const float*)d_in[4];
    const float* b2 = (const float*)d_in[5];
    const float* W3 = (const float*)d_in[6];
    const float* b3 = (const float*)d_in[7];
    float* out = (float*)d_out;

    __half *H1, *H2, *Zf, *WT1, *WT2, *WT3;
    cudaGetSymbolAddress((void**)&H1,  g_H1);
    cudaGetSymbolAddress((void**)&H2,  g_H2);
    cudaGetSymbolAddress((void**)&Zf,  g_Zf);
    cudaGetSymbolAddress((void**)&WT1, g_WT1);
    cudaGetSymbolAddress((void**)&WT2, g_WT2);
    cudaGetSymbolAddress((void**)&WT3, g_WT3);

    cudaFuncSetAttribute(gemm_nt_f16, cudaFuncAttributeMaxDynamicSharedMemorySize, NTF_SMEM);
    cudaFuncSetAttribute(gemm_enc<64,  true,  false>, cudaFuncAttributeMaxDynamicSharedMemorySize, ENC_SMEM);
    cudaFuncSetAttribute(gemm_enc<512, false, false>, cudaFuncAttributeMaxDynamicSharedMemorySize, ENC_SMEM);
    cudaFuncSetAttribute(gemm_enc<512, false, true>,  cudaFuncAttributeMaxDynamicSharedMemorySize, ENC_SMEM);

    prep_wt<<<(DIM * HID + 255) / 256, 256>>>(W1, WT1, DIM, HID);
    prep_wt<<<(HID * HID + 255) / 256, 256>>>(W2, WT2, HID, HID);
    prep_wt<<<(HID * LAT + 255) / 256, 256>>>(W3, WT3, HID, LAT);

    // Layer 1 (fp32 x/y fused in one launch)
    dim3 g1(HID / 128, 2 * NR / 128);
    gemm_enc<64, true, false><<<g1, 256, ENC_SMEM>>>(x, y, WT1, b1, H1, HID);

    // Layer 2 (fp16 A)
    dim3 g2(HID / 128, 2 * NR / 128);
    gemm_enc<512, false, false><<<g2, 256, ENC_SMEM>>>(H1, nullptr, WT2, b2, H2, HID);

    // Layer 3 + L2 normalize -> fp16 Z
    dim3 g3(1, 2 * NR / 128);
    gemm_enc<512, false, true><<<g3, 256, ENC_SMEM>>>(H2, nullptr, WT3, b3, Zf, LAT);

    // Similarity (single-pass fp16)
    dim3 g4(NR / 128, NR / 128);
    gemm_nt_f16<<<g4, 256, NTF_SMEM>>>(Zf, Zf + (size_t)NR * LAT, out);
}

// round 9
// speedup vs baseline: 3.6092x; 1.0650x over previous
#include <cuda_runtime.h>
#include <cuda_bf16.h>
#include <cuda_fp16.h>
#include <math.h>
#include <cstdint>

#define NR   8192
#define DIM  64
#define HID  512
#define LAT  128

// Scratch (device globals — allocation-free per harness rules)
__device__ __half g_H1[2 * NR * HID];    // 16 MB
__device__ __half g_H2[2 * NR * HID];    // 16 MB
__device__ __half g_Zf[2 * NR * LAT];    //  4 MB
__device__ __half g_WT1[HID * DIM];
__device__ __half g_WT2[HID * HID];
__device__ __half g_WT3[LAT * HID];

// ===========================================================================
// helpers
// ===========================================================================
__device__ __forceinline__ uint32_t smem_u32(const void* p) {
    uint32_t a;
    asm("{ .reg .u64 t; cvta.to.shared.u64 t, %1; cvt.u32.u64 %0, t; }"
        : "=r"(a) : "l"(p));
    return a;
}
__device__ __forceinline__ void ldmx4(uint32_t* r, uint32_t addr) {
    asm volatile("ldmatrix.sync.aligned.m8n8.x4.shared.b16 {%0,%1,%2,%3}, [%4];"
                 : "=r"(r[0]), "=r"(r[1]), "=r"(r[2]), "=r"(r[3]) : "r"(addr));
}
__device__ __forceinline__ void mma16816h(float* d, const uint32_t* a,
                                          uint32_t b0, uint32_t b1) {
    asm volatile(
        "mma.sync.aligned.m16n8k16.row.col.f32.f16.f16.f32 "
        "{%0,%1,%2,%3}, {%4,%5,%6,%7}, {%8,%9}, {%0,%1,%2,%3};"
        : "+f"(d[0]), "+f"(d[1]), "+f"(d[2]), "+f"(d[3])
        : "r"(a[0]), "r"(a[1]), "r"(a[2]), "r"(a[3]), "r"(b0), "r"(b1));
}
__device__ __forceinline__ void cpa16(uint32_t dst, const void* src) {
    asm volatile("cp.async.cg.shared.global [%0], [%1], 16;"
                 :: "r"(dst), "l"(src));
}
#define CP_COMMIT() asm volatile("cp.async.commit_group;")
#define CP_WAIT0()  asm volatile("cp.async.wait_group 0;" ::: "memory")
#define CP_WAIT1()  asm volatile("cp.async.wait_group 1;" ::: "memory")

__device__ __forceinline__ uint32_t packh2(float a, float b) {
    uint32_t r;
    asm("cvt.rn.f16x2.f32 %0, %1, %2;" : "=r"(r) : "f"(b), "f"(a));
    return r;
}

// ===========================================================================
// prep: WT[n*K+k] = fp16(W[k*N+n])
// ===========================================================================
__global__ void prep_wt(const float* __restrict__ W,
                        __half* __restrict__ WT, int K, int N) {
    int idx = blockIdx.x * blockDim.x + threadIdx.x;
    if (idx >= K * N) return;
    int n = idx / K, k = idx - n * K;
    WT[idx] = __float2half(W[(size_t)k * N + n]);
}

// ===========================================================================
// Encoder mma GEMM, single-pass fp16, double-buffered (round-8 validated).
// CTA 128x128, BK=64, 8 warps (4x2), 2 CTAs/SM.
// ===========================================================================
#define ESTR      144
#define ET        (128 * ESTR)
#define ENC_SMEM  (4 * ET)

template<int K, bool A_FP32, bool NORM>
__global__ __launch_bounds__(256, 2) void gemm_enc(
    const void* __restrict__ Ax, const void* __restrict__ Ay,
    const __half* __restrict__ B,
    const float* __restrict__ bias,
    __half* __restrict__ Cf, int Ntot)
{
    constexpr int CH = K / 64;
    extern __shared__ char smem[];
    const uint32_t sbase = smem_u32(smem);
    const int tid = threadIdx.x;
    const int bmg = blockIdx.y << 7, bn = blockIdx.x << 7;
    const int wid = tid >> 5, lane = tid & 31;
    const int wm = (wid & 3) << 5, wn = (wid >> 2) << 6;
    const int lrow = lane & 15, khalf = lane >> 4;

    const float* Af32 = nullptr;
    const __half* Af16 = nullptr;
    int bm;
    if (A_FP32) {
        Af32 = (bmg < NR) ? (const float*)Ax : (const float*)Ay;
        bm = (bmg < NR) ? bmg : bmg - NR;
    } else {
        Af16 = (const __half*)Ax;
        bm = bmg;
    }

    float acc[2][8][4];
#pragma unroll
    for (int mt = 0; mt < 2; mt++)
#pragma unroll
        for (int nt = 0; nt < 8; nt++)
#pragma unroll
            for (int e = 0; e < 4; e++) acc[mt][nt][e] = 0.f;

    const int lr  = tid >> 1;
    const int ksg = (tid & 1) << 5;

    auto load_chunk = [&](int c, int buf) {
        const uint32_t abase = sbase + (uint32_t)(buf * 2) * ET;
        const uint32_t bbase = abase + ET;
        const uint32_t ob = (uint32_t)lr * ESTR + (uint32_t)ksg * 2;
        if (A_FP32) {
            const float* ap = Af32 + (size_t)(bm + lr) * K + c * 64 + ksg;
#pragma unroll
            for (int q = 0; q < 4; q++) {
                float4 f0 = *(const float4*)(ap + q * 8);
                float4 f1 = *(const float4*)(ap + q * 8 + 4);
                uint4 v;
                v.x = packh2(f0.x, f0.y); v.y = packh2(f0.z, f0.w);
                v.z = packh2(f1.x, f1.y); v.w = packh2(f1.z, f1.w);
                *(uint4*)(smem + (abase - sbase) + ob + q * 16) = v;
            }
        } else {
            const char* ap = (const char*)(Af16 + (size_t)(bm + lr) * K + c * 64 + ksg);
#pragma unroll
            for (int q = 0; q < 4; q++)
                cpa16(abase + ob + q * 16, ap + q * 16);
        }
        const char* bp = (const char*)(B + (size_t)(bn + lr) * K + c * 64 + ksg);
#pragma unroll
        for (int q = 0; q < 4; q++)
            cpa16(bbase + ob + q * 16, bp + q * 16);
    };

    load_chunk(0, 0);
    CP_COMMIT();

    for (int c = 0; c < CH; c++) {
        if (c + 1 < CH) {
            load_chunk(c + 1, (c + 1) & 1);
            CP_COMMIT();
            CP_WAIT1();
        } else {
            CP_WAIT0();
        }
        __syncthreads();

        const uint32_t abase = sbase + (uint32_t)((c & 1) * 2) * ET;
        const uint32_t bbase = abase + ET;
#pragma unroll
        for (int ks = 0; ks < 4; ks++) {
            const uint32_t koff = (uint32_t)ks * 32 + (uint32_t)khalf * 16;
            uint32_t a[2][4];
#pragma unroll
            for (int mt = 0; mt < 2; mt++) {
                const uint32_t ra = (uint32_t)(wm + mt * 16 + lrow) * ESTR + koff;
                ldmx4(a[mt], abase + ra);
            }
#pragma unroll
            for (int np = 0; np < 4; np++) {
                const uint32_t rb = (uint32_t)(wn + np * 16 + lrow) * ESTR + koff;
                uint32_t t[4];
                ldmx4(t, bbase + rb);
#pragma unroll
                for (int mt = 0; mt < 2; mt++) {
                    mma16816h(acc[mt][2*np+0], a[mt], t[0], t[2]);
                    mma16816h(acc[mt][2*np+1], a[mt], t[1], t[3]);
                }
            }
        }
        __syncthreads();
    }

    const int r_in = lane >> 2;
    const int c_in = (lane & 3) << 1;

    float bias2[8][2];
#pragma unroll
    for (int nt = 0; nt < 8; nt++) {
        bias2[nt][0] = bias[bn + wn + nt * 8 + c_in];
        bias2[nt][1] = bias[bn + wn + nt * 8 + c_in + 1];
    }

    if (!NORM) {
#pragma unroll
        for (int mt = 0; mt < 2; mt++) {
            const int r0 = bmg + wm + mt * 16 + r_in;
#pragma unroll
            for (int nt = 0; nt < 8; nt++) {
                float o0 = fmaxf(acc[mt][nt][0] + bias2[nt][0], 0.f);
                float o1 = fmaxf(acc[mt][nt][1] + bias2[nt][1], 0.f);
                float o2 = fmaxf(acc[mt][nt][2] + bias2[nt][0], 0.f);
                float o3 = fmaxf(acc[mt][nt][3] + bias2[nt][1], 0.f);
                const int col = bn + wn + nt * 8 + c_in;
                *(uint32_t*)(Cf + (size_t)r0 * Ntot + col)       = packh2(o0, o1);
                *(uint32_t*)(Cf + (size_t)(r0 + 8) * Ntot + col) = packh2(o2, o3);
            }
        }
    } else {
        float ss[2][2];
#pragma unroll
        for (int mt = 0; mt < 2; mt++) { ss[mt][0] = 0.f; ss[mt][1] = 0.f; }
#pragma unroll
        for (int mt = 0; mt < 2; mt++)
#pragma unroll
            for (int nt = 0; nt < 8; nt++) {
                acc[mt][nt][0] += bias2[nt][0];
                acc[mt][nt][1] += bias2[nt][1];
                acc[mt][nt][2] += bias2[nt][0];
                acc[mt][nt][3] += bias2[nt][1];
                ss[mt][0] = fmaf(acc[mt][nt][0], acc[mt][nt][0],
                            fmaf(acc[mt][nt][1], acc[mt][nt][1], ss[mt][0]));
                ss[mt][1] = fmaf(acc[mt][nt][2], acc[mt][nt][2],
                            fmaf(acc[mt][nt][3], acc[mt][nt][3], ss[mt][1]));
            }
#pragma unroll
        for (int m = 1; m <= 2; m <<= 1) {
#pragma unroll
            for (int mt = 0; mt < 2; mt++) {
                ss[mt][0] += __shfl_xor_sync(0xFFFFFFFFu, ss[mt][0], m);
                ss[mt][1] += __shfl_xor_sync(0xFFFFFFFFu, ss[mt][1], m);
            }
        }
        float* red = (float*)smem;
        float* invp = red + 256;
        const int half = wid >> 2;
        if ((lane & 3) == 0) {
#pragma unroll
            for (int mt = 0; mt < 2; mt++) {
                red[(wm + mt * 16 + r_in) * 2 + half]     = ss[mt][0];
                red[(wm + mt * 16 + r_in + 8) * 2 + half] = ss[mt][1];
            }
        }
        __syncthreads();
        if (tid < 128) {
            float s = red[tid * 2] + red[tid * 2 + 1];
            invp[tid] = 1.f / fmaxf(sqrtf(s), 1e-12f);
        }
        __syncthreads();
#pragma unroll
        for (int mt = 0; mt < 2; mt++) {
            const int rl = wm + mt * 16 + r_in;
            const float inv0 = invp[rl], inv1 = invp[rl + 8];
            const int r0 = bmg + rl;
#pragma unroll
            for (int nt = 0; nt < 8; nt++) {
                const int col = wn + nt * 8 + c_in;
                *(uint32_t*)(Cf + (size_t)r0 * Ntot + col) =
                    packh2(acc[mt][nt][0] * inv0, acc[mt][nt][1] * inv0);
                *(uint32_t*)(Cf + (size_t)(r0 + 8) * Ntot + col) =
                    packh2(acc[mt][nt][2] * inv1, acc[mt][nt][3] * inv1);
            }
        }
    }
}

// ===========================================================================
// Final NT GEMM, strip-persistent: each CTA computes a 128x512 strip of
// C = Zx @ Zy^T (K=128). A tile loaded ONCE; 4 B tiles double-buffered via
// cp.async; per-tile epilogues spread DRAM writes. 8 warps 4x2, 2 CTAs/SM.
// ===========================================================================
#define FSTR      272
#define F_A       0
#define F_B0      (128 * FSTR)
#define F_B1      (F_B0 + 128 * FSTR)
#define NTF_SMEM  (3 * 128 * FSTR)       // 104448 B

__global__ __launch_bounds__(256, 2) void gemm_nt_f16(
    const __half* __restrict__ ZA, const __half* __restrict__ ZB,
    float* __restrict__ C)
{
    extern __shared__ char smem[];
    const uint32_t sbase = smem_u32(smem);
    const int tid = threadIdx.x;
    const int bm = blockIdx.y << 7;          // 128-row strip
    const int bn = blockIdx.x << 9;          // 512-col strip (4 tiles)

    const int row  = tid >> 1;
    const int half = tid & 1;
    const uint32_t dof = (uint32_t)row * FSTR + (uint32_t)half * 128;

    // ---- load A tile (once) + B tile 0; group 0 ----
    {
        const char* sa = (const char*)(ZA + (size_t)(bm + row) * LAT + half * 64);
        const char* sb = (const char*)(ZB + (size_t)(bn + row) * LAT + half * 64);
#pragma unroll
        for (int c = 0; c < 8; c++) {
            cpa16(sbase + F_A  + dof + c * 16, sa + c * 16);
            cpa16(sbase + F_B0 + dof + c * 16, sb + c * 16);
        }
    }
    CP_COMMIT();

    const int wid  = tid >> 5;
    const int lane = tid & 31;
    const int wm = (wid & 3) << 5;
    const int wn = (wid >> 2) << 6;
    const int lrow  = lane & 15;
    const int khalf = lane >> 4;
    const int r_in = lane >> 2;
    const int c_in = (lane & 3) << 1;

#pragma unroll
    for (int t = 0; t < 4; t++) {
        // prefetch next B tile into the other buffer, then wait for current
        if (t < 3) {
            const int brow = bn + (t + 1) * 128 + row;
            const char* sb = (const char*)(ZB + (size_t)brow * LAT + half * 64);
            const uint32_t bbuf = ((t + 1) & 1) ? F_B1 : F_B0;
#pragma unroll
            for (int c = 0; c < 8; c++)
                cpa16(sbase + bbuf + dof + c * 16, sb + c * 16);
            CP_COMMIT();
            CP_WAIT1();
        } else {
            CP_WAIT0();
        }
        __syncthreads();

        const uint32_t bbase = sbase + ((t & 1) ? F_B1 : F_B0);

        float acc[2][8][4];
#pragma unroll
        for (int mt = 0; mt < 2; mt++)
#pragma unroll
            for (int nt = 0; nt < 8; nt++)
#pragma unroll
                for (int e = 0; e < 4; e++) acc[mt][nt][e] = 0.f;

#pragma unroll
        for (int ks = 0; ks < 8; ks++) {
            const uint32_t koff = (uint32_t)ks * 32 + (uint32_t)khalf * 16;
            uint32_t a[2][4];
#pragma unroll
            for (int mt = 0; mt < 2; mt++) {
                const uint32_t ra = (uint32_t)(wm + mt * 16 + lrow) * FSTR + koff;
                ldmx4(a[mt], sbase + F_A + ra);
            }
#pragma unroll
            for (int np = 0; np < 4; np++) {
                const uint32_t rb = (uint32_t)(wn + np * 16 + lrow) * FSTR + koff;
                uint32_t b[4];
                ldmx4(b, bbase + rb);
#pragma unroll
                for (int mt = 0; mt < 2; mt++) {
                    mma16816h(acc[mt][2*np+0], a[mt], b[0], b[2]);
                    mma16816h(acc[mt][2*np+1], a[mt], b[1], b[3]);
                }
            }
        }

        // per-tile epilogue (spreads DRAM writes)
        const int r0 = bm + wm + r_in;
        const int c0 = bn + t * 128 + wn + c_in;
#pragma unroll
        for (int mt = 0; mt < 2; mt++) {
#pragma unroll
            for (int nt = 0; nt < 8; nt++) {
                float* p0 = C + (size_t)(r0 + mt * 16)     * NR + c0 + nt * 8;
                float* p1 = C + (size_t)(r0 + mt * 16 + 8) * NR + c0 + nt * 8;
                *(float2*)p0 = make_float2(acc[mt][nt][0], acc[mt][nt][1]);
                *(float2*)p1 = make_float2(acc[mt][nt][2], acc[mt][nt][3]);
            }
        }
        __syncthreads();   // buffer reuse guard
    }
}

// ===========================================================================
extern "C" void kernel_launch(void* const* d_in, const int* in_sizes, int n_in,
                              void* d_out, int out_size)
{
    const float* x  = (const float*)d_in[0];
    const float* y  = (const float*)d_in[1];
    const float* W1 = (const float*)d_in[2];
    const float* b1 = (const float*)d_in[3];
    const float* W2 = (const float*)d_in[4];
    const float* b2 = (const float*)d_in[5];
    const float* W3 = (const float*)d_in[6];
    const float* b3 = (const float*)d_in[7];
    float* out = (float*)d_out;

    __half *H1, *H2, *Zf, *WT1, *WT2, *WT3;
    cudaGetSymbolAddress((void**)&H1,  g_H1);
    cudaGetSymbolAddress((void**)&H2,  g_H2);
    cudaGetSymbolAddress((void**)&Zf,  g_Zf);
    cudaGetSymbolAddress((void**)&WT1, g_WT1);
    cudaGetSymbolAddress((void**)&WT2, g_WT2);
    cudaGetSymbolAddress((void**)&WT3, g_WT3);

    cudaFuncSetAttribute(gemm_nt_f16, cudaFuncAttributeMaxDynamicSharedMemorySize, NTF_SMEM);
    cudaFuncSetAttribute(gemm_enc<64,  true,  false>, cudaFuncAttributeMaxDynamicSharedMemorySize, ENC_SMEM);
    cudaFuncSetAttribute(gemm_enc<512, false, false>, cudaFuncAttributeMaxDynamicSharedMemorySize, ENC_SMEM);
    cudaFuncSetAttribute(gemm_enc<512, false, true>,  cudaFuncAttributeMaxDynamicSharedMemorySize, ENC_SMEM);

    prep_wt<<<(DIM * HID + 255) / 256, 256>>>(W1, WT1, DIM, HID);
    prep_wt<<<(HID * HID + 255) / 256, 256>>>(W2, WT2, HID, HID);
    prep_wt<<<(HID * LAT + 255) / 256, 256>>>(W3, WT3, HID, LAT);

    // Layer 1 (fp32 x/y fused in one launch)
    dim3 g1(HID / 128, 2 * NR / 128);
    gemm_enc<64, true, false><<<g1, 256, ENC_SMEM>>>(x, y, WT1, b1, H1, HID);

    // Layer 2 (fp16 A)
    dim3 g2(HID / 128, 2 * NR / 128);
    gemm_enc<512, false, false><<<g2, 256, ENC_SMEM>>>(H1, nullptr, WT2, b2, H2, HID);

    // Layer 3 + L2 normalize -> fp16 Z
    dim3 g3(1, 2 * NR / 128);
    gemm_enc<512, false, true><<<g3, 256, ENC_SMEM>>>(H2, nullptr, WT3, b3, Zf, LAT);

    // Similarity (strip-persistent fp16 NT)
    dim3 g4(NR / 512, NR / 128);
    gemm_nt_f16<<<g4, 256, NTF_SMEM>>>(Zf, Zf + (size_t)NR * LAT, out);
}